// round 10
// baseline (speedup 1.0000x reference)
#include <cuda_runtime.h>
#include <cuda_fp16.h>
#include <math.h>
#include <stdint.h>

// ---------------------------------------------------------------------------
// FastMKAAttention — round 9: attention with register online-softmax +
// cp.async double-buffered K/V; merged k/v GEMM launch.
// shapes: b=2, t=1024, d=2048, h=16, dh=128
// output tuple (floats): out[4194304] | kh[4194304] | vh[4194304] | lam[6144]
// ---------------------------------------------------------------------------

#define B_   2
#define T_   1024
#define D_   2048
#define H_   16
#define DH_  128
#define MROWS (B_*T_)          // 2048
#define NELEM (B_*T_*D_)       // 4194304

// fp32 scratch
__device__ float g_q[NELEM];            // q fp32 (attention consumes)
__device__ float g_l2[NELEM];           // EMA
__device__ float g_hdn[MROWS*(D_/2)];   // router hidden

// fp16 scratch
__device__ __half g_x16[NELEM];
__device__ __half g_wq16[D_*D_];
__device__ __half g_wk16[D_*D_];
__device__ __half g_wv16[D_*D_];
__device__ __half g_wo16[D_*D_];
__device__ __half g_rw116[(D_/2)*D_];
__device__ __half g_q16[NELEM];
__device__ __half g_f16[NELEM];
__device__ __half g_a16[NELEM];

// ---------------------------------------------------------------------------
// helpers
// ---------------------------------------------------------------------------
__device__ __forceinline__ void cp_async16(void* dst, const void* src) {
    unsigned s = (unsigned)__cvta_generic_to_shared(dst);
    asm volatile("cp.async.cg.shared.global [%0], [%1], 16;" :: "r"(s), "l"(src));
}
#define CP_COMMIT asm volatile("cp.async.commit_group;")
#define CP_WAIT0  asm volatile("cp.async.wait_group 0;")

__device__ __forceinline__ void mma_fp16(float* c, const unsigned* a, const unsigned* b) {
    asm volatile(
        "mma.sync.aligned.m16n8k16.row.col.f32.f16.f16.f32 "
        "{%0,%1,%2,%3}, {%4,%5,%6,%7}, {%8,%9}, {%0,%1,%2,%3};\n"
        : "+f"(c[0]), "+f"(c[1]), "+f"(c[2]), "+f"(c[3])
        : "r"(a[0]), "r"(a[1]), "r"(a[2]), "r"(a[3]), "r"(b[0]), "r"(b[1]));
}

// ---------------------------------------------------------------------------
// convert kernels: fp32 -> fp16
// ---------------------------------------------------------------------------
__global__ void cvt_kernel(const float* __restrict__ src,
                           __half* __restrict__ dst, int n)
{
    int i = (blockIdx.x * blockDim.x + threadIdx.x) * 4;
    if (i >= n) return;
    float4 v = *(const float4*)(src + i);
    *(__half2*)(dst + i)     = __floats2half2_rn(v.x, v.y);
    *(__half2*)(dst + i + 2) = __floats2half2_rn(v.z, v.w);
}

__global__ void cvt3_kernel(const float* __restrict__ s0, __half* __restrict__ d0,
                            const float* __restrict__ s1, __half* __restrict__ d1,
                            const float* __restrict__ s2, __half* __restrict__ d2,
                            int n)
{
    const float* src = (blockIdx.y == 0) ? s0 : (blockIdx.y == 1) ? s1 : s2;
    __half* dst      = (blockIdx.y == 0) ? d0 : (blockIdx.y == 1) ? d1 : d2;
    int i = (blockIdx.x * blockDim.x + threadIdx.x) * 4;
    if (i >= n) return;
    float4 v = *(const float4*)(src + i);
    *(__half2*)(dst + i)     = __floats2half2_rn(v.x, v.y);
    *(__half2*)(dst + i + 2) = __floats2half2_rn(v.z, v.w);
}

// ---------------------------------------------------------------------------
// fp16 mma GEMM, single pass, cp.async double buffer. (mainloop = R7 proven)
// grid.z==2 selects (Bm,C) for z=0 / (Bm2,C2) for z=1 (merged k/v GEMM).
// ---------------------------------------------------------------------------
#define SSTR 40
#define HELEMS (128*SSTR)
#define STAGE_ELEMS (2*HELEMS)
#define STAGE_BYTES (STAGE_ELEMS*2)
#define GEMM_SMEM (2*STAGE_BYTES)     // 40960 B

__device__ __forceinline__ void stage_tile(
    const __half* __restrict__ A, const __half* __restrict__ Bm,
    __half* sbuf, int bm, int bn, int kt, int K, int tid)
{
    const __half* ga = A  + (size_t)bm * K + kt;
    const __half* gb = Bm + (size_t)bn * K + kt;
#pragma unroll
    for (int p = 0; p < 2; p++) {
        int idx = p * 256 + tid;
        int row = idx >> 2;
        int c8  = (idx & 3) * 8;
        cp_async16(sbuf + row * SSTR + c8,          ga + (size_t)row * K + c8);
        cp_async16(sbuf + HELEMS + row * SSTR + c8, gb + (size_t)row * K + c8);
    }
}

template<int MODE, int ACT, int F16OUT>
__global__ __launch_bounds__(256) void mma_gemm_tn(
    const __half* __restrict__ A, const __half* __restrict__ Bm,
    const __half* __restrict__ Bm2,
    const float* __restrict__ bias, float* __restrict__ C, float* __restrict__ C2,
    __half* __restrict__ C16,
    int M, int N, int K)
{
    extern __shared__ __half smem[];

    const __half* Bsel = (blockIdx.z == 1) ? Bm2 : Bm;
    float*        Csel = (blockIdx.z == 1) ? C2  : C;

    const int tid  = threadIdx.x;
    const int lane = tid & 31;
    const int wid  = tid >> 5;
    const int wm   = wid >> 2;
    const int wn   = wid & 3;
    const int bm   = blockIdx.y * 128;
    const int bn   = blockIdx.x * 128;

    float acc[4][4][4];
#pragma unroll
    for (int i = 0; i < 4; i++)
#pragma unroll
        for (int j = 0; j < 4; j++)
#pragma unroll
            for (int r = 0; r < 4; r++) acc[i][j][r] = 0.f;

    const int nt = K / 32;
    stage_tile(A, Bsel, smem, bm, bn, 0, K, tid);
    CP_COMMIT;

    for (int it = 0; it < nt; it++) {
        CP_WAIT0;
        __syncthreads();
        if (it + 1 < nt) {
            stage_tile(A, Bsel, smem + ((it + 1) & 1) * STAGE_ELEMS,
                       bm, bn, (it + 1) * 32, K, tid);
            CP_COMMIT;
        }
        const __half* As = smem + (it & 1) * STAGE_ELEMS;
        const __half* Bs = As + HELEMS;

#pragma unroll
        for (int ks = 0; ks < 2; ks++) {
            const int kk = ks * 16 + (lane & 3) * 2;
            unsigned af[4][4];
#pragma unroll
            for (int mf = 0; mf < 4; mf++) {
                int r0 = (wm * 64 + mf * 16 + (lane >> 2)) * SSTR;
                int r1 = r0 + 8 * SSTR;
                af[mf][0] = *(const unsigned*)&As[r0 + kk];
                af[mf][1] = *(const unsigned*)&As[r1 + kk];
                af[mf][2] = *(const unsigned*)&As[r0 + kk + 8];
                af[mf][3] = *(const unsigned*)&As[r1 + kk + 8];
            }
            unsigned bf[4][2];
#pragma unroll
            for (int nf = 0; nf < 4; nf++) {
                int c0 = (wn * 32 + nf * 8 + (lane >> 2)) * SSTR;
                bf[nf][0] = *(const unsigned*)&Bs[c0 + kk];
                bf[nf][1] = *(const unsigned*)&Bs[c0 + kk + 8];
            }
#pragma unroll
            for (int mf = 0; mf < 4; mf++)
#pragma unroll
                for (int nf = 0; nf < 4; nf++)
                    mma_fp16(acc[mf][nf], af[mf], bf[nf]);
        }
        __syncthreads();
    }

    // epilogue
#pragma unroll
    for (int mf = 0; mf < 4; mf++) {
#pragma unroll
        for (int nf = 0; nf < 4; nf++) {
            int m0 = bm + wm * 64 + mf * 16 + (lane >> 2);
            int n  = bn + wn * 32 + nf * 8 + (lane & 3) * 2;
#pragma unroll
            for (int half = 0; half < 2; half++) {
                int m = m0 + half * 8;
                float2 v;
                v.x = acc[mf][nf][half * 2 + 0];
                v.y = acc[mf][nf][half * 2 + 1];
                if (ACT == 1) {
                    v.x += bias[n];
                    v.y += bias[n + 1];
                    v.x = v.x / (1.f + __expf(-v.x));
                    v.y = v.y / (1.f + __expf(-v.y));
                }
                if (MODE == 0) {
                    size_t idx = (size_t)m * N + n;
                    if (Csel) *(float2*)&Csel[idx] = v;
                    if (F16OUT == 1)
                        *(__half2*)&C16[idx] = __floats2half2_rn(v.x, v.y);
                } else {
                    size_t idx = (size_t)(m >> 10) * (H_*T_*DH_) + (size_t)(n >> 7) * (T_*DH_)
                               + (size_t)(m & 1023) * DH_ + (n & 127);
                    *(float2*)&Csel[idx] = v;
                }
            }
        }
    }
}

// ---------------------------------------------------------------------------
// causal EMA — parallel scan (unchanged from R8)
// ---------------------------------------------------------------------------
#define EMA_L  64
#define EMA_NC 16
#define BETA64 1.1790184577738583e-3f   // 0.9^64

__global__ __launch_bounds__(256) void ema_scan_kernel(
    const float* __restrict__ x, float* __restrict__ l2)
{
    __shared__ float s_end[EMA_NC][17];
    __shared__ float s_cin[EMA_NC][17];

    const int tid   = threadIdx.x;
    const int cloc  = tid & 15;
    const int chunk = tid >> 4;
    const int ch    = blockIdx.x * 16 + cloc;
    const int b     = ch >> 11;
    const int d     = ch & (D_ - 1);

    const float beta = 0.9f, omb = 0.1f;
    const size_t base = (size_t)b * T_ * D_ + d;
    const size_t p0   = base + (size_t)chunk * EMA_L * D_;

    float loc[EMA_L];
    float s = 0.f;
#pragma unroll
    for (int i = 0; i < EMA_L; i++) {
        s = beta * s + omb * x[p0 + (size_t)i * D_];
        loc[i] = s;
    }
    s_end[chunk][cloc] = s;
    __syncthreads();

    if (chunk == 0) {
        float S = 0.f;
#pragma unroll
        for (int k = 0; k < EMA_NC; k++) {
            s_cin[k][cloc] = S;
            S = s_end[k][cloc] + BETA64 * S;
        }
    }
    __syncthreads();

    const float cin = s_cin[chunk][cloc];
    float pw = beta;
#pragma unroll
    for (int i = 0; i < EMA_L; i++) {
        l2[p0 + (size_t)i * D_] = loc[i] + pw * cin;
        pw *= beta;
    }
}

// ---------------------------------------------------------------------------
// router + fused combine (unchanged)
// ---------------------------------------------------------------------------
__global__ __launch_bounds__(256) void router_fuse(
    const float* __restrict__ hdn, const float* __restrict__ rw2,
    const float* __restrict__ rb2, const float* __restrict__ x,
    const float* __restrict__ l2, const float* __restrict__ l3m,
    float* __restrict__ lam_out, __half* __restrict__ f16)
{
    const int m = blockIdx.x;
    const int tid = threadIdx.x;
    const int HD = D_ / 2;

    const float* hrow = hdn + (size_t)m * HD;
    float s0 = 0.f, s1 = 0.f, s2 = 0.f;
    for (int k = tid; k < HD; k += 256) {
        float hv = hrow[k];
        s0 += hv * rw2[k];
        s1 += hv * rw2[HD + k];
        s2 += hv * rw2[2*HD + k];
    }
#pragma unroll
    for (int o = 16; o > 0; o >>= 1) {
        s0 += __shfl_down_sync(0xffffffffu, s0, o);
        s1 += __shfl_down_sync(0xffffffffu, s1, o);
        s2 += __shfl_down_sync(0xffffffffu, s2, o);
    }
    __shared__ float red[8][3];
    __shared__ float lam_s[3];
    if ((tid & 31) == 0) {
        red[tid >> 5][0] = s0; red[tid >> 5][1] = s1; red[tid >> 5][2] = s2;
    }
    __syncthreads();
    if (tid == 0) {
        float L0 = rb2[0], L1 = rb2[1], L2v = rb2[2];
        for (int w = 0; w < 8; w++) { L0 += red[w][0]; L1 += red[w][1]; L2v += red[w][2]; }
        float mx = fmaxf(L0, fmaxf(L1, L2v));
        float e0 = __expf(L0 - mx), e1 = __expf(L1 - mx), e2 = __expf(L2v - mx);
        float inv = 1.f / (e0 + e1 + e2);
        lam_s[0] = e0 * inv; lam_s[1] = e1 * inv; lam_s[2] = e2 * inv;
        lam_out[m*3+0] = lam_s[0]; lam_out[m*3+1] = lam_s[1]; lam_out[m*3+2] = lam_s[2];
    }
    __syncthreads();
    const float la = lam_s[0], lb = lam_s[1], lc = lam_s[2];
    const int b = m >> 10;
    const float4* xr  = (const float4*)(x  + (size_t)m * D_);
    const float4* l2r = (const float4*)(l2 + (size_t)m * D_);
    const float4* l3r = (const float4*)(l3m + (size_t)b * D_);
    for (int q = tid; q < D_/4; q += 256) {
        float4 xv = xr[q], l2v = l2r[q], l3v = l3r[q];
        float o0 = la*xv.x + lb*l2v.x + lc*l3v.x;
        float o1 = la*xv.y + lb*l2v.y + lc*l3v.y;
        float o2 = la*xv.z + lb*l2v.z + lc*l3v.z;
        float o3 = la*xv.w + lb*l2v.w + lc*l3v.w;
        size_t base = (size_t)m * D_ + q * 4;
        *(__half2*)&f16[base]     = __floats2half2_rn(o0, o1);
        *(__half2*)&f16[base + 2] = __floats2half2_rn(o2, o3);
    }
}

// ---------------------------------------------------------------------------
// flash-style causal attention (fp32), register online-softmax, cp.async
// double-buffered K/V, 2 paired q-tiles per block. Emits fp16.
// smem: Qs 64x132 | K0,V0,K1,V1 64x132 each | Ss 64xSST  = 186624 B
// ---------------------------------------------------------------------------
#define SST 69
#define ATT_SMEM ((5*64*132 + 64*SST) * 4)

__global__ __launch_bounds__(256) void attn_kernel(
    const float* __restrict__ qsrc, const float* __restrict__ kh,
    const float* __restrict__ vh, __half* __restrict__ o16)
{
    extern __shared__ float sm[];
    float* Qs = sm;                       // 64 x 132
    float* KV = Qs + 64*132;              // 4 tiles of 64 x 132
    float* Ss = Qs + 5*64*132;            // 64 x SST

    const int tid = threadIdx.x;
    const int bh = blockIdx.y;
    const int b = bh >> 4, h = bh & 15;
    const float scale = 0.08838834764831845f;  // 1/sqrt(128)

    const int i_sc = tid >> 2;   // row 0..63
    const int jg   = tid & 3;    // key group (stride-4)
    const int ck   = tid & 3;    // dim group (dims ck*4 + q*16)

    const float* kbase = kh + (size_t)(b*H_ + h) * T_ * DH_;
    const float* vbase = vh + (size_t)(b*H_ + h) * T_ * DH_;

#pragma unroll 1
    for (int pass = 0; pass < 2; pass++) {
        const int qt = (pass == 0) ? (int)blockIdx.x : 15 - (int)blockIdx.x;
        const int q0 = qt * 64;

        __syncthreads();  // protect Qs/KV reuse across passes

        // load Q tile (scaled)
#pragma unroll
        for (int p = 0; p < 8; p++) {
            int f = p * 256 + tid;
            int i = f >> 5, c4 = f & 31;
            float4 v = *(const float4*)&qsrc[(size_t)(b*T_ + q0 + i)*D_ + h*DH_ + c4*4];
            v.x *= scale; v.y *= scale; v.z *= scale; v.w *= scale;
            *(float4*)&Qs[i*132 + c4*4] = v;
        }

        // stage K/V tile 0 into buffer 0
        {
            float* Kd = KV; float* Vd = KV + 64*132;
#pragma unroll
            for (int p = 0; p < 8; p++) {
                int f = p * 256 + tid;
                int j = f >> 5, c4 = f & 31;
                cp_async16(&Kd[j*132 + c4*4], &kbase[(size_t)j*DH_ + c4*4]);
                cp_async16(&Vd[j*132 + c4*4], &vbase[(size_t)j*DH_ + c4*4]);
            }
            CP_COMMIT;
        }

        float m = -1e30f, l = 0.f;
        float acc[32];
#pragma unroll
        for (int c = 0; c < 32; c++) acc[c] = 0.f;

        for (int kt = 0; kt <= qt; kt++) {
            CP_WAIT0;
            __syncthreads();   // tile kt ready everywhere; prev compute done
            if (kt < qt) {     // stage kt+1 into other buffer
                float* Kd = KV + ((kt + 1) & 1) * 2 * 64 * 132;
                float* Vd = Kd + 64*132;
                const float* kg = kbase + (size_t)(kt + 1) * 64 * DH_;
                const float* vg = vbase + (size_t)(kt + 1) * 64 * DH_;
#pragma unroll
                for (int p = 0; p < 8; p++) {
                    int f = p * 256 + tid;
                    int j = f >> 5, c4 = f & 31;
                    cp_async16(&Kd[j*132 + c4*4], &kg[(size_t)j*DH_ + c4*4]);
                    cp_async16(&Vd[j*132 + c4*4], &vg[(size_t)j*DH_ + c4*4]);
                }
                CP_COMMIT;
            }
            const float* Ks = KV + (kt & 1) * 2 * 64 * 132;
            const float* Vs = Ks + 64*132;

            // scores: thread (i_sc, jg) computes keys j = jg + jj*4
            float sum[16];
#pragma unroll
            for (int jj = 0; jj < 16; jj++) sum[jj] = 0.f;
            const float4* qrow = (const float4*)&Qs[i_sc * 132];
            for (int c4 = 0; c4 < 32; c4++) {
                float4 qv = qrow[c4];
#pragma unroll
                for (int jj = 0; jj < 16; jj++) {
                    float4 kv = *(const float4*)&Ks[(jg + jj*4)*132 + c4*4];
                    sum[jj] += qv.x*kv.x + qv.y*kv.y + qv.z*kv.z + qv.w*kv.w;
                }
            }
            const int gq = q0 + i_sc;
#pragma unroll
            for (int jj = 0; jj < 16; jj++) {
                int gk = kt*64 + jg + jj*4;
                if (gk > gq) sum[jj] = -1e30f;
            }

            // register online softmax: combine over the 4-lane group
            float mloc = m;
#pragma unroll
            for (int jj = 0; jj < 16; jj++) mloc = fmaxf(mloc, sum[jj]);
            mloc = fmaxf(mloc, __shfl_xor_sync(0xffffffffu, mloc, 1));
            mloc = fmaxf(mloc, __shfl_xor_sync(0xffffffffu, mloc, 2));
            float alpha = __expf(m - mloc);
            float ls = 0.f;
#pragma unroll
            for (int jj = 0; jj < 16; jj++) {
                float pv = __expf(sum[jj] - mloc);
                Ss[i_sc*SST + jg + jj*4] = pv;
                ls += pv;
            }
            ls += __shfl_xor_sync(0xffffffffu, ls, 1);
            ls += __shfl_xor_sync(0xffffffffu, ls, 2);
            m = mloc;
            l = l * alpha + ls;
            __syncwarp();   // Ss row written by this warp's 4-lane groups

            // PV: thread (i_sc, ck) owns dims ck*4 + q*16
#pragma unroll
            for (int c = 0; c < 32; c++) acc[c] *= alpha;
            const float* srow = &Ss[i_sc * SST];
            for (int j = 0; j < 64; j++) {
                float pv = srow[j];
                const float* vrow = &Vs[j*132 + ck*4];
#pragma unroll
                for (int q = 0; q < 8; q++) {
                    float4 vv = *(const float4*)&vrow[q*16];
                    acc[q*4+0] += pv * vv.x;
                    acc[q*4+1] += pv * vv.y;
                    acc[q*4+2] += pv * vv.z;
                    acc[q*4+3] += pv * vv.w;
                }
            }
            __syncwarp();   // Ss reads done before next tile overwrites
        }

        // output (fp16); l replicated across the 4-lane group
        const float inv = 1.f / l;
        size_t orow = (size_t)(b*T_ + q0 + i_sc)*D_ + h*DH_;
#pragma unroll
        for (int q = 0; q < 8; q++) {
            int d = ck*4 + q*16;
            *(__half2*)&o16[orow + d]     = __floats2half2_rn(acc[q*4+0]*inv, acc[q*4+1]*inv);
            *(__half2*)&o16[orow + d + 2] = __floats2half2_rn(acc[q*4+2]*inv, acc[q*4+3]*inv);
        }
    }
}

// ---------------------------------------------------------------------------
extern "C" void kernel_launch(void* const* d_in, const int* in_sizes, int n_in,
                              void* d_out, int out_size)
{
    const float* x   = (const float*)d_in[0];
    const float* l3m = (const float*)d_in[1];
    const float* wq  = (const float*)d_in[2];
    const float* wk  = (const float*)d_in[3];
    const float* wv  = (const float*)d_in[4];
    const float* wo  = (const float*)d_in[5];
    const float* rw1 = (const float*)d_in[6];
    const float* rb1 = (const float*)d_in[7];
    const float* rw2 = (const float*)d_in[8];
    const float* rb2 = (const float*)d_in[9];

    float* out  = (float*)d_out;
    float* khp  = out + (size_t)NELEM;
    float* vhp  = khp + (size_t)NELEM;
    float* lamp = vhp + (size_t)NELEM;

    float *qs, *l2s, *hdns;
    cudaGetSymbolAddress((void**)&qs,   g_q);
    cudaGetSymbolAddress((void**)&l2s,  g_l2);
    cudaGetSymbolAddress((void**)&hdns, g_hdn);
    __half *x16,*wq16,*wk16,*wv16,*wo16,*r116,*q16,*f16,*a16;
    cudaGetSymbolAddress((void**)&x16,  g_x16);
    cudaGetSymbolAddress((void**)&wq16, g_wq16);
    cudaGetSymbolAddress((void**)&wk16, g_wk16);
    cudaGetSymbolAddress((void**)&wv16, g_wv16);
    cudaGetSymbolAddress((void**)&wo16, g_wo16);
    cudaGetSymbolAddress((void**)&r116, g_rw116);
    cudaGetSymbolAddress((void**)&q16,  g_q16);
    cudaGetSymbolAddress((void**)&f16,  g_f16);
    cudaGetSymbolAddress((void**)&a16,  g_a16);

    dim3 blk(256);

    cudaFuncSetAttribute(mma_gemm_tn<0,0,1>, cudaFuncAttributeMaxDynamicSharedMemorySize, GEMM_SMEM);
    cudaFuncSetAttribute(mma_gemm_tn<0,0,0>, cudaFuncAttributeMaxDynamicSharedMemorySize, GEMM_SMEM);
    cudaFuncSetAttribute(mma_gemm_tn<0,1,0>, cudaFuncAttributeMaxDynamicSharedMemorySize, GEMM_SMEM);
    cudaFuncSetAttribute(mma_gemm_tn<1,0,0>, cudaFuncAttributeMaxDynamicSharedMemorySize, GEMM_SMEM);
    cudaFuncSetAttribute(attn_kernel, cudaFuncAttributeMaxDynamicSharedMemorySize, ATT_SMEM);

    // launch #1-#3, then q-GEMM at our slot #4 (ncu capture slot)
    cvt_kernel<<<NELEM/1024, 256>>>(x,   x16,  NELEM);        // 1
    cvt_kernel<<<(D_*D_)/1024, 256>>>(wq, wq16, D_*D_);       // 2
    ema_scan_kernel<<<(B_*D_)/16, 256>>>(x, l2s);             // 3
    mma_gemm_tn<0,0,1><<<dim3(D_/128, MROWS/128), blk, GEMM_SMEM>>>(  // 4 <- profiled
        x16, wq16, nullptr, nullptr, qs, nullptr, q16, MROWS, D_, D_);

    // remaining conversions
    cvt3_kernel<<<dim3((D_*D_)/1024, 3), 256>>>(wk, wk16, wv, wv16, wo, wo16, D_*D_);
    cvt_kernel<<<((D_/2)*D_)/1024, 256>>>(rw1, r116, (D_/2)*D_);

    // hdn = silu(q @ rw1^T + rb1)
    mma_gemm_tn<0,1,0><<<dim3((D_/2)/128, MROWS/128), blk, GEMM_SMEM>>>(
        q16, r116, nullptr, rb1, hdns, nullptr, nullptr, MROWS, D_/2, D_);
    // lam + fused (fp16)
    router_fuse<<<MROWS, 256>>>(hdns, rw2, rb2, x, l2s, l3m, lamp, f16);
    // kh + vh in ONE launch (grid.z selects weight/dest), scattered [b,h,t,dh]
    mma_gemm_tn<1,0,0><<<dim3(D_/128, MROWS/128, 2), blk, GEMM_SMEM>>>(
        f16, wk16, wv16, nullptr, khp, vhp, nullptr, MROWS, D_, D_);
    // attention: paired q-tiles {qt, 15-qt}, 8x32 grid
    attn_kernel<<<dim3(8, B_*H_), blk, ATT_SMEM>>>(qs, khp, vhp, a16);
    // out = attn @ wo^T
    mma_gemm_tn<0,0,0><<<dim3(D_/128, MROWS/128), blk, GEMM_SMEM>>>(
        a16, wo16, nullptr, nullptr, out, nullptr, nullptr, MROWS, D_, D_);
}

// round 12
// speedup vs baseline: 2.1524x; 2.1524x over previous
#include <cuda_runtime.h>
#include <cuda_fp16.h>
#include <math.h>
#include <stdint.h>

// ---------------------------------------------------------------------------
// FastMKAAttention — round 12: R11 tensor-core attention with FIXED cp.async
// staging index math (Q: 128x16 chunks, K: 64x16 chunks, V: 128x8 chunks).
// shapes: b=2, t=1024, d=2048, h=16, dh=128
// output tuple (floats): out[4194304] | kh[4194304] | vh[4194304] | lam[6144]
// ---------------------------------------------------------------------------

#define B_   2
#define T_   1024
#define D_   2048
#define H_   16
#define DH_  128
#define MROWS (B_*T_)          // 2048
#define NELEM (B_*T_*D_)       // 4194304

// fp32 scratch
__device__ float g_l2[NELEM];           // EMA
__device__ float g_hdn[MROWS*(D_/2)];   // router hidden

// fp16 scratch
__device__ __half g_x16[NELEM];
__device__ __half g_wq16[D_*D_];
__device__ __half g_wk16[D_*D_];
__device__ __half g_wv16[D_*D_];
__device__ __half g_wo16[D_*D_];
__device__ __half g_rw116[(D_/2)*D_];
__device__ __half g_qh16[NELEM];        // q hi (also feeds router GEMM)
__device__ __half g_ql16[NELEM];        // q lo
__device__ __half g_f16[NELEM];         // fused (fp16)
__device__ __half g_kh16[NELEM];        // K hi  [b,h,t,dh]
__device__ __half g_kl16[NELEM];        // K lo  [b,h,t,dh]
__device__ __half g_vt16[NELEM];        // V fp16 transposed [b,h,dh,t]
__device__ __half g_a16[NELEM];         // attention out (fp16)

// ---------------------------------------------------------------------------
// helpers
// ---------------------------------------------------------------------------
__device__ __forceinline__ void cp_async16(void* dst, const void* src) {
    unsigned s = (unsigned)__cvta_generic_to_shared(dst);
    asm volatile("cp.async.cg.shared.global [%0], [%1], 16;" :: "r"(s), "l"(src));
}
#define CP_COMMIT asm volatile("cp.async.commit_group;")
#define CP_WAIT0  asm volatile("cp.async.wait_group 0;")

__device__ __forceinline__ void mma_fp16(float* c, const unsigned* a, const unsigned* b) {
    asm volatile(
        "mma.sync.aligned.m16n8k16.row.col.f32.f16.f16.f32 "
        "{%0,%1,%2,%3}, {%4,%5,%6,%7}, {%8,%9}, {%0,%1,%2,%3};\n"
        : "+f"(c[0]), "+f"(c[1]), "+f"(c[2]), "+f"(c[3])
        : "r"(a[0]), "r"(a[1]), "r"(a[2]), "r"(a[3]), "r"(b[0]), "r"(b[1]));
}

__device__ __forceinline__ unsigned packh2(float a, float b) {
    __half2 h = __floats2half2_rn(a, b);
    return *(unsigned*)&h;
}

// ---------------------------------------------------------------------------
// convert kernels: fp32 -> fp16
// ---------------------------------------------------------------------------
__global__ void cvt_kernel(const float* __restrict__ src,
                           __half* __restrict__ dst, int n)
{
    int i = (blockIdx.x * blockDim.x + threadIdx.x) * 4;
    if (i >= n) return;
    float4 v = *(const float4*)(src + i);
    *(__half2*)(dst + i)     = __floats2half2_rn(v.x, v.y);
    *(__half2*)(dst + i + 2) = __floats2half2_rn(v.z, v.w);
}

__global__ void cvt3_kernel(const float* __restrict__ s0, __half* __restrict__ d0,
                            const float* __restrict__ s1, __half* __restrict__ d1,
                            const float* __restrict__ s2, __half* __restrict__ d2,
                            int n)
{
    const float* src = (blockIdx.y == 0) ? s0 : (blockIdx.y == 1) ? s1 : s2;
    __half* dst      = (blockIdx.y == 0) ? d0 : (blockIdx.y == 1) ? d1 : d2;
    int i = (blockIdx.x * blockDim.x + threadIdx.x) * 4;
    if (i >= n) return;
    float4 v = *(const float4*)(src + i);
    *(__half2*)(dst + i)     = __floats2half2_rn(v.x, v.y);
    *(__half2*)(dst + i + 2) = __floats2half2_rn(v.z, v.w);
}

// ---------------------------------------------------------------------------
// fp16 mma GEMM (mainloop unchanged / proven).
// MODE 0: row-major. MODE 1: scatter [b,h,t,dh]; grid.z selects wk/wv.
// F16OUT: 0 none; 2 = write ONLY fp16 hi/lo (C16/C16b), skip fp32;
//         3 = MODE1 extras: z=0 -> kh16/kl16 (C16/C16b); z=1 -> vt16 (C16c).
// ---------------------------------------------------------------------------
#define SSTR 40
#define HELEMS (128*SSTR)
#define STAGE_ELEMS (2*HELEMS)
#define STAGE_BYTES (STAGE_ELEMS*2)
#define GEMM_SMEM (2*STAGE_BYTES)     // 40960 B

__device__ __forceinline__ void stage_tile(
    const __half* __restrict__ A, const __half* __restrict__ Bm,
    __half* sbuf, int bm, int bn, int kt, int K, int tid)
{
    const __half* ga = A  + (size_t)bm * K + kt;
    const __half* gb = Bm + (size_t)bn * K + kt;
#pragma unroll
    for (int p = 0; p < 2; p++) {
        int idx = p * 256 + tid;
        int row = idx >> 2;
        int c8  = (idx & 3) * 8;
        cp_async16(sbuf + row * SSTR + c8,          ga + (size_t)row * K + c8);
        cp_async16(sbuf + HELEMS + row * SSTR + c8, gb + (size_t)row * K + c8);
    }
}

template<int MODE, int ACT, int F16OUT>
__global__ __launch_bounds__(256) void mma_gemm_tn(
    const __half* __restrict__ A, const __half* __restrict__ Bm,
    const __half* __restrict__ Bm2,
    const float* __restrict__ bias, float* __restrict__ C, float* __restrict__ C2,
    __half* __restrict__ C16, __half* __restrict__ C16b, __half* __restrict__ C16c,
    int M, int N, int K)
{
    extern __shared__ __half smem[];

    const __half* Bsel = (blockIdx.z == 1) ? Bm2 : Bm;
    float*        Csel = (blockIdx.z == 1) ? C2  : C;

    const int tid  = threadIdx.x;
    const int lane = tid & 31;
    const int wid  = tid >> 5;
    const int wm   = wid >> 2;
    const int wn   = wid & 3;
    const int bm   = blockIdx.y * 128;
    const int bn   = blockIdx.x * 128;

    float acc[4][4][4];
#pragma unroll
    for (int i = 0; i < 4; i++)
#pragma unroll
        for (int j = 0; j < 4; j++)
#pragma unroll
            for (int r = 0; r < 4; r++) acc[i][j][r] = 0.f;

    const int nt = K / 32;
    stage_tile(A, Bsel, smem, bm, bn, 0, K, tid);
    CP_COMMIT;

    for (int it = 0; it < nt; it++) {
        CP_WAIT0;
        __syncthreads();
        if (it + 1 < nt) {
            stage_tile(A, Bsel, smem + ((it + 1) & 1) * STAGE_ELEMS,
                       bm, bn, (it + 1) * 32, K, tid);
            CP_COMMIT;
        }
        const __half* As = smem + (it & 1) * STAGE_ELEMS;
        const __half* Bs = As + HELEMS;

#pragma unroll
        for (int ks = 0; ks < 2; ks++) {
            const int kk = ks * 16 + (lane & 3) * 2;
            unsigned af[4][4];
#pragma unroll
            for (int mf = 0; mf < 4; mf++) {
                int r0 = (wm * 64 + mf * 16 + (lane >> 2)) * SSTR;
                int r1 = r0 + 8 * SSTR;
                af[mf][0] = *(const unsigned*)&As[r0 + kk];
                af[mf][1] = *(const unsigned*)&As[r1 + kk];
                af[mf][2] = *(const unsigned*)&As[r0 + kk + 8];
                af[mf][3] = *(const unsigned*)&As[r1 + kk + 8];
            }
            unsigned bf[4][2];
#pragma unroll
            for (int nf = 0; nf < 4; nf++) {
                int c0 = (wn * 32 + nf * 8 + (lane >> 2)) * SSTR;
                bf[nf][0] = *(const unsigned*)&Bs[c0 + kk];
                bf[nf][1] = *(const unsigned*)&Bs[c0 + kk + 8];
            }
#pragma unroll
            for (int mf = 0; mf < 4; mf++)
#pragma unroll
                for (int nf = 0; nf < 4; nf++)
                    mma_fp16(acc[mf][nf], af[mf], bf[nf]);
        }
        __syncthreads();
    }

    // epilogue
#pragma unroll
    for (int mf = 0; mf < 4; mf++) {
#pragma unroll
        for (int nf = 0; nf < 4; nf++) {
            int m0 = bm + wm * 64 + mf * 16 + (lane >> 2);
            int n  = bn + wn * 32 + nf * 8 + (lane & 3) * 2;
#pragma unroll
            for (int half = 0; half < 2; half++) {
                int m = m0 + half * 8;
                float2 v;
                v.x = acc[mf][nf][half * 2 + 0];
                v.y = acc[mf][nf][half * 2 + 1];
                if (ACT == 1) {
                    v.x += bias[n];
                    v.y += bias[n + 1];
                    v.x = v.x / (1.f + __expf(-v.x));
                    v.y = v.y / (1.f + __expf(-v.y));
                }
                if (MODE == 0) {
                    size_t idx = (size_t)m * N + n;
                    if (F16OUT == 2) {
                        __half2 hh = __floats2half2_rn(v.x, v.y);
                        *(__half2*)&C16[idx] = hh;
                        float lx = v.x - __half2float(__low2half(hh));
                        float ly = v.y - __half2float(__high2half(hh));
                        *(__half2*)&C16b[idx] = __floats2half2_rn(lx, ly);
                    } else {
                        if (C) *(float2*)&C[idx] = v;
                        if (F16OUT == 1)
                            *(__half2*)&C16[idx] = __floats2half2_rn(v.x, v.y);
                    }
                } else {
                    size_t idx = (size_t)(m >> 10) * (H_*T_*DH_) + (size_t)(n >> 7) * (T_*DH_)
                               + (size_t)(m & 1023) * DH_ + (n & 127);
                    *(float2*)&Csel[idx] = v;
                    if (F16OUT == 3) {
                        if (blockIdx.z == 0) {
                            __half2 hh = __floats2half2_rn(v.x, v.y);
                            *(__half2*)&C16[idx] = hh;
                            float lx = v.x - __half2float(__low2half(hh));
                            float ly = v.y - __half2float(__high2half(hh));
                            *(__half2*)&C16b[idx] = __floats2half2_rn(lx, ly);
                        } else {
                            size_t tb = ((size_t)((m >> 10) * H_ + (n >> 7)) * DH_
                                         + (n & 127)) * T_ + (m & 1023);
                            C16c[tb]      = __float2half(v.x);
                            C16c[tb + T_] = __float2half(v.y);
                        }
                    }
                }
            }
        }
    }
}

// ---------------------------------------------------------------------------
// causal EMA — parallel scan (unchanged)
// ---------------------------------------------------------------------------
#define EMA_L  64
#define EMA_NC 16
#define BETA64 1.1790184577738583e-3f   // 0.9^64

__global__ __launch_bounds__(256) void ema_scan_kernel(
    const float* __restrict__ x, float* __restrict__ l2)
{
    __shared__ float s_end[EMA_NC][17];
    __shared__ float s_cin[EMA_NC][17];

    const int tid   = threadIdx.x;
    const int cloc  = tid & 15;
    const int chunk = tid >> 4;
    const int ch    = blockIdx.x * 16 + cloc;
    const int b     = ch >> 11;
    const int d     = ch & (D_ - 1);

    const float beta = 0.9f, omb = 0.1f;
    const size_t base = (size_t)b * T_ * D_ + d;
    const size_t p0   = base + (size_t)chunk * EMA_L * D_;

    float loc[EMA_L];
    float s = 0.f;
#pragma unroll
    for (int i = 0; i < EMA_L; i++) {
        s = beta * s + omb * x[p0 + (size_t)i * D_];
        loc[i] = s;
    }
    s_end[chunk][cloc] = s;
    __syncthreads();

    if (chunk == 0) {
        float S = 0.f;
#pragma unroll
        for (int k = 0; k < EMA_NC; k++) {
            s_cin[k][cloc] = S;
            S = s_end[k][cloc] + BETA64 * S;
        }
    }
    __syncthreads();

    const float cin = s_cin[chunk][cloc];
    float pw = beta;
#pragma unroll
    for (int i = 0; i < EMA_L; i++) {
        l2[p0 + (size_t)i * D_] = loc[i] + pw * cin;
        pw *= beta;
    }
}

// ---------------------------------------------------------------------------
// router + fused combine (unchanged)
// ---------------------------------------------------------------------------
__global__ __launch_bounds__(256) void router_fuse(
    const float* __restrict__ hdn, const float* __restrict__ rw2,
    const float* __restrict__ rb2, const float* __restrict__ x,
    const float* __restrict__ l2, const float* __restrict__ l3m,
    float* __restrict__ lam_out, __half* __restrict__ f16)
{
    const int m = blockIdx.x;
    const int tid = threadIdx.x;
    const int HD = D_ / 2;

    const float* hrow = hdn + (size_t)m * HD;
    float s0 = 0.f, s1 = 0.f, s2 = 0.f;
    for (int k = tid; k < HD; k += 256) {
        float hv = hrow[k];
        s0 += hv * rw2[k];
        s1 += hv * rw2[HD + k];
        s2 += hv * rw2[2*HD + k];
    }
#pragma unroll
    for (int o = 16; o > 0; o >>= 1) {
        s0 += __shfl_down_sync(0xffffffffu, s0, o);
        s1 += __shfl_down_sync(0xffffffffu, s1, o);
        s2 += __shfl_down_sync(0xffffffffu, s2, o);
    }
    __shared__ float red[8][3];
    __shared__ float lam_s[3];
    if ((tid & 31) == 0) {
        red[tid >> 5][0] = s0; red[tid >> 5][1] = s1; red[tid >> 5][2] = s2;
    }
    __syncthreads();
    if (tid == 0) {
        float L0 = rb2[0], L1 = rb2[1], L2v = rb2[2];
        for (int w = 0; w < 8; w++) { L0 += red[w][0]; L1 += red[w][1]; L2v += red[w][2]; }
        float mx = fmaxf(L0, fmaxf(L1, L2v));
        float e0 = __expf(L0 - mx), e1 = __expf(L1 - mx), e2 = __expf(L2v - mx);
        float inv = 1.f / (e0 + e1 + e2);
        lam_s[0] = e0 * inv; lam_s[1] = e1 * inv; lam_s[2] = e2 * inv;
        lam_out[m*3+0] = lam_s[0]; lam_out[m*3+1] = lam_s[1]; lam_out[m*3+2] = lam_s[2];
    }
    __syncthreads();
    const float la = lam_s[0], lb = lam_s[1], lc = lam_s[2];
    const int b = m >> 10;
    const float4* xr  = (const float4*)(x  + (size_t)m * D_);
    const float4* l2r = (const float4*)(l2 + (size_t)m * D_);
    const float4* l3r = (const float4*)(l3m + (size_t)b * D_);
    for (int q = tid; q < D_/4; q += 256) {
        float4 xv = xr[q], l2v = l2r[q], l3v = l3r[q];
        float o0 = la*xv.x + lb*l2v.x + lc*l3v.x;
        float o1 = la*xv.y + lb*l2v.y + lc*l3v.y;
        float o2 = la*xv.z + lb*l2v.z + lc*l3v.z;
        float o3 = la*xv.w + lb*l2v.w + lc*l3v.w;
        size_t base = (size_t)m * D_ + q * 4;
        *(__half2*)&f16[base]     = __floats2half2_rn(o0, o1);
        *(__half2*)&f16[base + 2] = __floats2half2_rn(o2, o3);
    }
}

// ---------------------------------------------------------------------------
// tensor-core causal attention.
// CTA: 128 q-rows x full K stream (64-key tiles). 8 warps x 16 rows.
// QK^T: 3-pass split fp16 (qh*kh + qh*kl + ql*kh). PV: fp16, P from registers.
// Paired q-blocks {i, 7-i}: grid (4, 32) = 128 CTAs, uniform 18 ktiles.
// smem: Qh/Ql [128 x 136] + 2 x (Kh,Kl [64 x 136] + Vt [128 x 72]) = 176128 B
// ---------------------------------------------------------------------------
#define QSTR 136
#define KSTR 136
#define VSTR 72
#define Q_HALVES (128*QSTR)
#define K_HALVES (64*KSTR)
#define V_HALVES (128*VSTR)
#define BUF_HALVES (2*K_HALVES + V_HALVES)
#define ATT_SMEM ((2*Q_HALVES + 2*BUF_HALVES)*2)

__global__ __launch_bounds__(256) void attn_mma_kernel(
    const __half* __restrict__ qh16, const __half* __restrict__ ql16,
    const __half* __restrict__ kh16, const __half* __restrict__ kl16,
    const __half* __restrict__ vt16, __half* __restrict__ o16)
{
    extern __shared__ __half hs[];
    __half* Qh  = hs;
    __half* Ql  = hs + Q_HALVES;
    __half* BUF = hs + 2 * Q_HALVES;

    const int tid  = threadIdx.x;
    const int lane = tid & 31;
    const int w    = tid >> 5;          // warp 0..7 -> rows w*16..w*16+15
    const int bh   = blockIdx.y;        // b*16+h
    const float scale = 0.08838834764831845f;  // 1/sqrt(128)

    const __half* kbase = kh16 + (size_t)bh * T_ * DH_;
    const __half* lbase = kl16 + (size_t)bh * T_ * DH_;
    const __half* vbase = vt16 + (size_t)bh * DH_ * T_;

#pragma unroll 1
    for (int pass = 0; pass < 2; pass++) {
        const int qb = (pass == 0) ? (int)blockIdx.x : 7 - (int)blockIdx.x;
        const int q0 = qb * 128;
        const int nkt = 2 * qb + 2;

        __syncthreads();  // previous pass reads done before restaging

        // stage Q hi/lo: 128 rows x 128 halves = 2048 16B-chunks each
        {
            const int b = bh >> 4, h = bh & 15;
            const __half* qh_g = qh16 + ((size_t)(b * T_ + q0)) * D_ + h * DH_;
            const __half* ql_g = ql16 + ((size_t)(b * T_ + q0)) * D_ + h * DH_;
#pragma unroll
            for (int p = 0; p < 8; p++) {
                int f = p * 256 + tid;          // 0..2047
                int r = f >> 4, c = (f & 15) * 8;
                cp_async16(Qh + r * QSTR + c, qh_g + (size_t)r * D_ + c);
                cp_async16(Ql + r * QSTR + c, ql_g + (size_t)r * D_ + c);
            }
        }
        // stage K/V tile 0
        {
            __half* Kd = BUF; __half* Ld = Kd + K_HALVES; __half* Vd = Ld + K_HALVES;
            // K hi/lo: 64 rows x 128 halves = 1024 chunks each
#pragma unroll
            for (int p = 0; p < 4; p++) {
                int f = p * 256 + tid;          // 0..1023
                int j = f >> 4, c = (f & 15) * 8;
                cp_async16(Kd + j * KSTR + c, kbase + (size_t)j * DH_ + c);
                cp_async16(Ld + j * KSTR + c, lbase + (size_t)j * DH_ + c);
            }
            // V^T: 128 dh-rows x 64 halves = 1024 chunks
#pragma unroll
            for (int p = 0; p < 4; p++) {
                int f = p * 256 + tid;          // 0..1023
                int dd = f >> 3, c = (f & 7) * 8;
                cp_async16(Vd + dd * VSTR + c, vbase + (size_t)dd * T_ + c);
            }
        }
        CP_COMMIT;

        float m0 = -1e30f, m8 = -1e30f, l0 = 0.f, l8 = 0.f;
        float Oacc[16][4];
#pragma unroll
        for (int nf = 0; nf < 16; nf++)
#pragma unroll
            for (int e = 0; e < 4; e++) Oacc[nf][e] = 0.f;

        const int r0g = q0 + w * 16 + (lane >> 2);
        const int r8g = r0g + 8;

        for (int kt = 0; kt < nkt; kt++) {
            CP_WAIT0;
            __syncthreads();
            if (kt + 1 < nkt) {
                __half* Kd = BUF + ((kt + 1) & 1) * BUF_HALVES;
                __half* Ld = Kd + K_HALVES; __half* Vd = Ld + K_HALVES;
                const __half* kg = kbase + (size_t)(kt + 1) * 64 * DH_;
                const __half* lg = lbase + (size_t)(kt + 1) * 64 * DH_;
                const __half* vg = vbase + (size_t)(kt + 1) * 64;
#pragma unroll
                for (int p = 0; p < 4; p++) {
                    int f = p * 256 + tid;
                    int j = f >> 4, c = (f & 15) * 8;
                    cp_async16(Kd + j * KSTR + c, kg + (size_t)j * DH_ + c);
                    cp_async16(Ld + j * KSTR + c, lg + (size_t)j * DH_ + c);
                }
#pragma unroll
                for (int p = 0; p < 4; p++) {
                    int f = p * 256 + tid;
                    int dd = f >> 3, c = (f & 7) * 8;
                    cp_async16(Vd + dd * VSTR + c, vg + (size_t)dd * T_ + c);
                }
                CP_COMMIT;
            }
            const __half* Kh_ = BUF + (kt & 1) * BUF_HALVES;
            const __half* Kl_ = Kh_ + K_HALVES;
            const __half* Vt_ = Kl_ + K_HALVES;

            // ---- scores: 3-pass split mma ----
            float facc[8][4];
#pragma unroll
            for (int nf = 0; nf < 8; nf++)
#pragma unroll
                for (int e = 0; e < 4; e++) facc[nf][e] = 0.f;

#pragma unroll
            for (int ks = 0; ks < 8; ks++) {
                const int ao = (w * 16 + (lane >> 2)) * QSTR + ks * 16 + (lane & 3) * 2;
                unsigned bhf[8][2], blf[8][2];
#pragma unroll
                for (int nf = 0; nf < 8; nf++) {
                    int bo = (nf * 8 + (lane >> 2)) * KSTR + ks * 16 + (lane & 3) * 2;
                    bhf[nf][0] = *(const unsigned*)&Kh_[bo];
                    bhf[nf][1] = *(const unsigned*)&Kh_[bo + 8];
                    blf[nf][0] = *(const unsigned*)&Kl_[bo];
                    blf[nf][1] = *(const unsigned*)&Kl_[bo + 8];
                }
                unsigned af[4];
                af[0] = *(const unsigned*)&Qh[ao];
                af[1] = *(const unsigned*)&Qh[ao + 8 * QSTR];
                af[2] = *(const unsigned*)&Qh[ao + 8];
                af[3] = *(const unsigned*)&Qh[ao + 8 * QSTR + 8];
#pragma unroll
                for (int nf = 0; nf < 8; nf++) mma_fp16(facc[nf], af, bhf[nf]);
#pragma unroll
                for (int nf = 0; nf < 8; nf++) mma_fp16(facc[nf], af, blf[nf]);
                af[0] = *(const unsigned*)&Ql[ao];
                af[1] = *(const unsigned*)&Ql[ao + 8 * QSTR];
                af[2] = *(const unsigned*)&Ql[ao + 8];
                af[3] = *(const unsigned*)&Ql[ao + 8 * QSTR + 8];
#pragma unroll
                for (int nf = 0; nf < 8; nf++) mma_fp16(facc[nf], af, bhf[nf]);
            }

            // ---- scale + causal mask ----
            const int colb = kt * 64 + (lane & 3) * 2;
#pragma unroll
            for (int nf = 0; nf < 8; nf++) {
                int c0 = colb + nf * 8, c1 = c0 + 1;
                float s0 = facc[nf][0] * scale; if (c0 > r0g) s0 = -1e30f;
                float s1 = facc[nf][1] * scale; if (c1 > r0g) s1 = -1e30f;
                float s2 = facc[nf][2] * scale; if (c0 > r8g) s2 = -1e30f;
                float s3 = facc[nf][3] * scale; if (c1 > r8g) s3 = -1e30f;
                facc[nf][0] = s0; facc[nf][1] = s1; facc[nf][2] = s2; facc[nf][3] = s3;
            }

            // ---- register online softmax (rows r0g / r8g) ----
            float mx0 = m0, mx8 = m8;
#pragma unroll
            for (int nf = 0; nf < 8; nf++) {
                mx0 = fmaxf(mx0, fmaxf(facc[nf][0], facc[nf][1]));
                mx8 = fmaxf(mx8, fmaxf(facc[nf][2], facc[nf][3]));
            }
            mx0 = fmaxf(mx0, __shfl_xor_sync(0xffffffffu, mx0, 1));
            mx0 = fmaxf(mx0, __shfl_xor_sync(0xffffffffu, mx0, 2));
            mx8 = fmaxf(mx8, __shfl_xor_sync(0xffffffffu, mx8, 1));
            mx8 = fmaxf(mx8, __shfl_xor_sync(0xffffffffu, mx8, 2));
            float a0 = __expf(m0 - mx0), a8 = __expf(m8 - mx8);
            float ls0 = 0.f, ls8 = 0.f;
#pragma unroll
            for (int nf = 0; nf < 8; nf++) {
                facc[nf][0] = __expf(facc[nf][0] - mx0); ls0 += facc[nf][0];
                facc[nf][1] = __expf(facc[nf][1] - mx0); ls0 += facc[nf][1];
                facc[nf][2] = __expf(facc[nf][2] - mx8); ls8 += facc[nf][2];
                facc[nf][3] = __expf(facc[nf][3] - mx8); ls8 += facc[nf][3];
            }
            ls0 += __shfl_xor_sync(0xffffffffu, ls0, 1);
            ls0 += __shfl_xor_sync(0xffffffffu, ls0, 2);
            ls8 += __shfl_xor_sync(0xffffffffu, ls8, 1);
            ls8 += __shfl_xor_sync(0xffffffffu, ls8, 2);
            m0 = mx0; m8 = mx8;
            l0 = l0 * a0 + ls0;
            l8 = l8 * a8 + ls8;
#pragma unroll
            for (int nf = 0; nf < 16; nf++) {
                Oacc[nf][0] *= a0; Oacc[nf][1] *= a0;
                Oacc[nf][2] *= a8; Oacc[nf][3] *= a8;
            }

            // ---- PV: P from registers (fp16), V^T from smem ----
#pragma unroll
            for (int kk = 0; kk < 4; kk++) {
                unsigned pa[4];
                pa[0] = packh2(facc[2*kk][0],   facc[2*kk][1]);
                pa[1] = packh2(facc[2*kk][2],   facc[2*kk][3]);
                pa[2] = packh2(facc[2*kk+1][0], facc[2*kk+1][1]);
                pa[3] = packh2(facc[2*kk+1][2], facc[2*kk+1][3]);
#pragma unroll
                for (int nf = 0; nf < 16; nf++) {
                    int vo = (nf * 8 + (lane >> 2)) * VSTR + kk * 16 + (lane & 3) * 2;
                    unsigned vb[2];
                    vb[0] = *(const unsigned*)&Vt_[vo];
                    vb[1] = *(const unsigned*)&Vt_[vo + 8];
                    mma_fp16(Oacc[nf], pa, vb);
                }
            }
        }

        // ---- output (fp16) ----
        const float i0 = 1.f / l0, i8 = 1.f / l8;
        const int b = bh >> 4, h = bh & 15;
        size_t row0 = ((size_t)(b * T_ + q0 + w * 16 + (lane >> 2))) * D_
                    + h * DH_ + (lane & 3) * 2;
#pragma unroll
        for (int nf = 0; nf < 16; nf++) {
            *(__half2*)&o16[row0 + nf * 8] =
                __floats2half2_rn(Oacc[nf][0] * i0, Oacc[nf][1] * i0);
            *(__half2*)&o16[row0 + 8 * D_ + nf * 8] =
                __floats2half2_rn(Oacc[nf][2] * i8, Oacc[nf][3] * i8);
        }
    }
}

// ---------------------------------------------------------------------------
extern "C" void kernel_launch(void* const* d_in, const int* in_sizes, int n_in,
                              void* d_out, int out_size)
{
    const float* x   = (const float*)d_in[0];
    const float* l3m = (const float*)d_in[1];
    const float* wq  = (const float*)d_in[2];
    const float* wk  = (const float*)d_in[3];
    const float* wv  = (const float*)d_in[4];
    const float* wo  = (const float*)d_in[5];
    const float* rw1 = (const float*)d_in[6];
    const float* rb1 = (const float*)d_in[7];
    const float* rw2 = (const float*)d_in[8];
    const float* rb2 = (const float*)d_in[9];

    float* out  = (float*)d_out;
    float* khp  = out + (size_t)NELEM;
    float* vhp  = khp + (size_t)NELEM;
    float* lamp = vhp + (size_t)NELEM;

    float *l2s, *hdns;
    cudaGetSymbolAddress((void**)&l2s,  g_l2);
    cudaGetSymbolAddress((void**)&hdns, g_hdn);
    __half *x16,*wq16,*wk16,*wv16,*wo16,*r116,*qh,*ql,*f16,*kh,*kl,*vt,*a16;
    cudaGetSymbolAddress((void**)&x16,  g_x16);
    cudaGetSymbolAddress((void**)&wq16, g_wq16);
    cudaGetSymbolAddress((void**)&wk16, g_wk16);
    cudaGetSymbolAddress((void**)&wv16, g_wv16);
    cudaGetSymbolAddress((void**)&wo16, g_wo16);
    cudaGetSymbolAddress((void**)&r116, g_rw116);
    cudaGetSymbolAddress((void**)&qh,   g_qh16);
    cudaGetSymbolAddress((void**)&ql,   g_ql16);
    cudaGetSymbolAddress((void**)&f16,  g_f16);
    cudaGetSymbolAddress((void**)&kh,   g_kh16);
    cudaGetSymbolAddress((void**)&kl,   g_kl16);
    cudaGetSymbolAddress((void**)&vt,   g_vt16);
    cudaGetSymbolAddress((void**)&a16,  g_a16);

    dim3 blk(256);

    cudaFuncSetAttribute(mma_gemm_tn<0,0,2>, cudaFuncAttributeMaxDynamicSharedMemorySize, GEMM_SMEM);
    cudaFuncSetAttribute(mma_gemm_tn<0,0,0>, cudaFuncAttributeMaxDynamicSharedMemorySize, GEMM_SMEM);
    cudaFuncSetAttribute(mma_gemm_tn<0,1,0>, cudaFuncAttributeMaxDynamicSharedMemorySize, GEMM_SMEM);
    cudaFuncSetAttribute(mma_gemm_tn<1,0,3>, cudaFuncAttributeMaxDynamicSharedMemorySize, GEMM_SMEM);
    cudaFuncSetAttribute(attn_mma_kernel, cudaFuncAttributeMaxDynamicSharedMemorySize, ATT_SMEM);

    // 1-3, then q-GEMM at slot #4 (ncu capture slot)
    cvt_kernel<<<NELEM/1024, 256>>>(x,   x16,  NELEM);
    cvt_kernel<<<(D_*D_)/1024, 256>>>(wq, wq16, D_*D_);
    ema_scan_kernel<<<(B_*D_)/16, 256>>>(x, l2s);
    // q = x @ wq^T -> fp16 hi/lo only
    mma_gemm_tn<0,0,2><<<dim3(D_/128, MROWS/128), blk, GEMM_SMEM>>>(
        x16, wq16, nullptr, nullptr, nullptr, nullptr, qh, ql, nullptr, MROWS, D_, D_);

    cvt3_kernel<<<dim3((D_*D_)/1024, 3), 256>>>(wk, wk16, wv, wv16, wo, wo16, D_*D_);
    cvt_kernel<<<((D_/2)*D_)/1024, 256>>>(rw1, r116, (D_/2)*D_);

    // hdn = silu(q @ rw1^T + rb1)   (uses q hi fp16)
    mma_gemm_tn<0,1,0><<<dim3((D_/2)/128, MROWS/128), blk, GEMM_SMEM>>>(
        qh, r116, nullptr, rb1, hdns, nullptr, nullptr, nullptr, nullptr, MROWS, D_/2, D_);
    // lam + fused (fp16)
    router_fuse<<<MROWS, 256>>>(hdns, rw2, rb2, x, l2s, l3m, lamp, f16);
    // kh + vh in one launch; z=0 also emits K hi/lo fp16, z=1 emits V^T fp16
    mma_gemm_tn<1,0,3><<<dim3(D_/128, MROWS/128, 2), blk, GEMM_SMEM>>>(
        f16, wk16, wv16, nullptr, khp, vhp, kh, kl, vt, MROWS, D_, D_);
    // tensor-core attention: paired q-blocks {i, 7-i}, grid (4, 32)
    attn_mma_kernel<<<dim3(4, B_*H_), blk, ATT_SMEM>>>(qh, ql, kh, kl, vt, a16);
    // out = attn @ wo^T
    mma_gemm_tn<0,0,0><<<dim3(D_/128, MROWS/128), blk, GEMM_SMEM>>>(
        a16, wo16, nullptr, nullptr, out, nullptr, nullptr, nullptr, nullptr, MROWS, D_, D_);
}

// round 13
// speedup vs baseline: 2.3711x; 1.1016x over previous
#include <cuda_runtime.h>
#include <cuda_fp16.h>
#include <math.h>
#include <stdint.h>

// ---------------------------------------------------------------------------
// FastMKAAttention — round 13: GEMM fragment loads via ldmatrix.x4
// (R12 attention + pipeline unchanged; only the GEMM inner loop changed)
// shapes: b=2, t=1024, d=2048, h=16, dh=128
// output tuple (floats): out[4194304] | kh[4194304] | vh[4194304] | lam[6144]
// ---------------------------------------------------------------------------

#define B_   2
#define T_   1024
#define D_   2048
#define H_   16
#define DH_  128
#define MROWS (B_*T_)          // 2048
#define NELEM (B_*T_*D_)       // 4194304

// fp32 scratch
__device__ float g_l2[NELEM];           // EMA
__device__ float g_hdn[MROWS*(D_/2)];   // router hidden

// fp16 scratch
__device__ __half g_x16[NELEM];
__device__ __half g_wq16[D_*D_];
__device__ __half g_wk16[D_*D_];
__device__ __half g_wv16[D_*D_];
__device__ __half g_wo16[D_*D_];
__device__ __half g_rw116[(D_/2)*D_];
__device__ __half g_qh16[NELEM];        // q hi (also feeds router GEMM)
__device__ __half g_ql16[NELEM];        // q lo
__device__ __half g_f16[NELEM];         // fused (fp16)
__device__ __half g_kh16[NELEM];        // K hi  [b,h,t,dh]
__device__ __half g_kl16[NELEM];        // K lo  [b,h,t,dh]
__device__ __half g_vt16[NELEM];        // V fp16 transposed [b,h,dh,t]
__device__ __half g_a16[NELEM];         // attention out (fp16)

// ---------------------------------------------------------------------------
// helpers
// ---------------------------------------------------------------------------
__device__ __forceinline__ void cp_async16(void* dst, const void* src) {
    unsigned s = (unsigned)__cvta_generic_to_shared(dst);
    asm volatile("cp.async.cg.shared.global [%0], [%1], 16;" :: "r"(s), "l"(src));
}
#define CP_COMMIT asm volatile("cp.async.commit_group;")
#define CP_WAIT0  asm volatile("cp.async.wait_group 0;")

__device__ __forceinline__ void mma_fp16(float* c, const unsigned* a, const unsigned* b) {
    asm volatile(
        "mma.sync.aligned.m16n8k16.row.col.f32.f16.f16.f32 "
        "{%0,%1,%2,%3}, {%4,%5,%6,%7}, {%8,%9}, {%0,%1,%2,%3};\n"
        : "+f"(c[0]), "+f"(c[1]), "+f"(c[2]), "+f"(c[3])
        : "r"(a[0]), "r"(a[1]), "r"(a[2]), "r"(a[3]), "r"(b[0]), "r"(b[1]));
}

__device__ __forceinline__ void ldsm_x4(unsigned* r, unsigned addr) {
    asm volatile("ldmatrix.sync.aligned.m8n8.x4.shared.b16 {%0,%1,%2,%3}, [%4];"
                 : "=r"(r[0]), "=r"(r[1]), "=r"(r[2]), "=r"(r[3]) : "r"(addr));
}

__device__ __forceinline__ unsigned packh2(float a, float b) {
    __half2 h = __floats2half2_rn(a, b);
    return *(unsigned*)&h;
}

// ---------------------------------------------------------------------------
// convert kernels: fp32 -> fp16
// ---------------------------------------------------------------------------
__global__ void cvt_kernel(const float* __restrict__ src,
                           __half* __restrict__ dst, int n)
{
    int i = (blockIdx.x * blockDim.x + threadIdx.x) * 4;
    if (i >= n) return;
    float4 v = *(const float4*)(src + i);
    *(__half2*)(dst + i)     = __floats2half2_rn(v.x, v.y);
    *(__half2*)(dst + i + 2) = __floats2half2_rn(v.z, v.w);
}

__global__ void cvt3_kernel(const float* __restrict__ s0, __half* __restrict__ d0,
                            const float* __restrict__ s1, __half* __restrict__ d1,
                            const float* __restrict__ s2, __half* __restrict__ d2,
                            int n)
{
    const float* src = (blockIdx.y == 0) ? s0 : (blockIdx.y == 1) ? s1 : s2;
    __half* dst      = (blockIdx.y == 0) ? d0 : (blockIdx.y == 1) ? d1 : d2;
    int i = (blockIdx.x * blockDim.x + threadIdx.x) * 4;
    if (i >= n) return;
    float4 v = *(const float4*)(src + i);
    *(__half2*)(dst + i)     = __floats2half2_rn(v.x, v.y);
    *(__half2*)(dst + i + 2) = __floats2half2_rn(v.z, v.w);
}

// ---------------------------------------------------------------------------
// fp16 mma GEMM with ldmatrix fragment loads (mapping validated in R5).
// MODE 0: row-major. MODE 1: scatter [b,h,t,dh]; grid.z selects wk/wv.
// F16OUT: 0 none; 2 = write ONLY fp16 hi/lo (C16/C16b), skip fp32;
//         3 = MODE1 extras: z=0 -> kh16/kl16 (C16/C16b); z=1 -> vt16 (C16c).
// ---------------------------------------------------------------------------
#define SSTR 40
#define HELEMS (128*SSTR)
#define STAGE_ELEMS (2*HELEMS)
#define STAGE_BYTES (STAGE_ELEMS*2)
#define GEMM_SMEM (2*STAGE_BYTES)     // 40960 B
#define ASTEP_B (16*SSTR*2)           // bytes between mf fragments
#define BSTEP_B (16*SSTR*2)           // bytes between nf-pair fragments

__device__ __forceinline__ void stage_tile(
    const __half* __restrict__ A, const __half* __restrict__ Bm,
    __half* sbuf, int bm, int bn, int kt, int K, int tid)
{
    const __half* ga = A  + (size_t)bm * K + kt;
    const __half* gb = Bm + (size_t)bn * K + kt;
#pragma unroll
    for (int p = 0; p < 2; p++) {
        int idx = p * 256 + tid;
        int row = idx >> 2;
        int c8  = (idx & 3) * 8;
        cp_async16(sbuf + row * SSTR + c8,          ga + (size_t)row * K + c8);
        cp_async16(sbuf + HELEMS + row * SSTR + c8, gb + (size_t)row * K + c8);
    }
}

template<int MODE, int ACT, int F16OUT>
__global__ __launch_bounds__(256) void mma_gemm_tn(
    const __half* __restrict__ A, const __half* __restrict__ Bm,
    const __half* __restrict__ Bm2,
    const float* __restrict__ bias, float* __restrict__ C, float* __restrict__ C2,
    __half* __restrict__ C16, __half* __restrict__ C16b, __half* __restrict__ C16c,
    int M, int N, int K)
{
    extern __shared__ __half smem[];
    const unsigned smem_u32 = (unsigned)__cvta_generic_to_shared(smem);

    const __half* Bsel = (blockIdx.z == 1) ? Bm2 : Bm;
    float*        Csel = (blockIdx.z == 1) ? C2  : C;

    const int tid  = threadIdx.x;
    const int lane = tid & 31;
    const int wid  = tid >> 5;
    const int wm   = wid >> 2;
    const int wn   = wid & 3;
    const int bm   = blockIdx.y * 128;
    const int bn   = blockIdx.x * 128;

    // ldmatrix per-lane byte offsets within a half-tile (validated in R5)
    const unsigned a_off = ((wm * 64 + (lane & 15)) * SSTR + (lane >> 4) * 8) * 2;
    const unsigned b_off = ((wn * 32 + (lane & 7) + ((lane >> 4) << 3)) * SSTR
                            + ((lane >> 3) & 1) * 8) * 2;

    float acc[4][4][4];
#pragma unroll
    for (int i = 0; i < 4; i++)
#pragma unroll
        for (int j = 0; j < 4; j++)
#pragma unroll
            for (int r = 0; r < 4; r++) acc[i][j][r] = 0.f;

    const int nt = K / 32;
    stage_tile(A, Bsel, smem, bm, bn, 0, K, tid);
    CP_COMMIT;

    for (int it = 0; it < nt; it++) {
        CP_WAIT0;
        __syncthreads();
        if (it + 1 < nt) {
            stage_tile(A, Bsel, smem + ((it + 1) & 1) * STAGE_ELEMS,
                       bm, bn, (it + 1) * 32, K, tid);
            CP_COMMIT;
        }
        const unsigned base   = smem_u32 + (it & 1) * STAGE_BYTES;
        const unsigned a_base = base + a_off;
        const unsigned b_base = base + HELEMS * 2 + b_off;

#pragma unroll
        for (int ks = 0; ks < 2; ks++) {
            const unsigned ko = ks * 32;   // 16 halves = 32 bytes
            unsigned af[4][4];
#pragma unroll
            for (int mf = 0; mf < 4; mf++)
                ldsm_x4(af[mf], a_base + mf * ASTEP_B + ko);
            // bq[p] = {bf[2p][0], bf[2p][1], bf[2p+1][0], bf[2p+1][1]}
            unsigned bq[2][4];
            ldsm_x4(bq[0], b_base + ko);
            ldsm_x4(bq[1], b_base + BSTEP_B + ko);
#pragma unroll
            for (int mf = 0; mf < 4; mf++)
#pragma unroll
                for (int nf = 0; nf < 4; nf++) {
                    unsigned bfr[2];
                    bfr[0] = bq[nf >> 1][(nf & 1) * 2 + 0];
                    bfr[1] = bq[nf >> 1][(nf & 1) * 2 + 1];
                    mma_fp16(acc[mf][nf], af[mf], bfr);
                }
        }
        __syncthreads();
    }

    // epilogue
#pragma unroll
    for (int mf = 0; mf < 4; mf++) {
#pragma unroll
        for (int nf = 0; nf < 4; nf++) {
            int m0 = bm + wm * 64 + mf * 16 + (lane >> 2);
            int n  = bn + wn * 32 + nf * 8 + (lane & 3) * 2;
#pragma unroll
            for (int half = 0; half < 2; half++) {
                int m = m0 + half * 8;
                float2 v;
                v.x = acc[mf][nf][half * 2 + 0];
                v.y = acc[mf][nf][half * 2 + 1];
                if (ACT == 1) {
                    v.x += bias[n];
                    v.y += bias[n + 1];
                    v.x = v.x / (1.f + __expf(-v.x));
                    v.y = v.y / (1.f + __expf(-v.y));
                }
                if (MODE == 0) {
                    size_t idx = (size_t)m * N + n;
                    if (F16OUT == 2) {
                        __half2 hh = __floats2half2_rn(v.x, v.y);
                        *(__half2*)&C16[idx] = hh;
                        float lx = v.x - __half2float(__low2half(hh));
                        float ly = v.y - __half2float(__high2half(hh));
                        *(__half2*)&C16b[idx] = __floats2half2_rn(lx, ly);
                    } else {
                        if (C) *(float2*)&C[idx] = v;
                        if (F16OUT == 1)
                            *(__half2*)&C16[idx] = __floats2half2_rn(v.x, v.y);
                    }
                } else {
                    size_t idx = (size_t)(m >> 10) * (H_*T_*DH_) + (size_t)(n >> 7) * (T_*DH_)
                               + (size_t)(m & 1023) * DH_ + (n & 127);
                    *(float2*)&Csel[idx] = v;
                    if (F16OUT == 3) {
                        if (blockIdx.z == 0) {
                            __half2 hh = __floats2half2_rn(v.x, v.y);
                            *(__half2*)&C16[idx] = hh;
                            float lx = v.x - __half2float(__low2half(hh));
                            float ly = v.y - __half2float(__high2half(hh));
                            *(__half2*)&C16b[idx] = __floats2half2_rn(lx, ly);
                        } else {
                            size_t tb = ((size_t)((m >> 10) * H_ + (n >> 7)) * DH_
                                         + (n & 127)) * T_ + (m & 1023);
                            C16c[tb]      = __float2half(v.x);
                            C16c[tb + T_] = __float2half(v.y);
                        }
                    }
                }
            }
        }
    }
}

// ---------------------------------------------------------------------------
// causal EMA — parallel scan (unchanged)
// ---------------------------------------------------------------------------
#define EMA_L  64
#define EMA_NC 16
#define BETA64 1.1790184577738583e-3f   // 0.9^64

__global__ __launch_bounds__(256) void ema_scan_kernel(
    const float* __restrict__ x, float* __restrict__ l2)
{
    __shared__ float s_end[EMA_NC][17];
    __shared__ float s_cin[EMA_NC][17];

    const int tid   = threadIdx.x;
    const int cloc  = tid & 15;
    const int chunk = tid >> 4;
    const int ch    = blockIdx.x * 16 + cloc;
    const int b     = ch >> 11;
    const int d     = ch & (D_ - 1);

    const float beta = 0.9f, omb = 0.1f;
    const size_t base = (size_t)b * T_ * D_ + d;
    const size_t p0   = base + (size_t)chunk * EMA_L * D_;

    float loc[EMA_L];
    float s = 0.f;
#pragma unroll
    for (int i = 0; i < EMA_L; i++) {
        s = beta * s + omb * x[p0 + (size_t)i * D_];
        loc[i] = s;
    }
    s_end[chunk][cloc] = s;
    __syncthreads();

    if (chunk == 0) {
        float S = 0.f;
#pragma unroll
        for (int k = 0; k < EMA_NC; k++) {
            s_cin[k][cloc] = S;
            S = s_end[k][cloc] + BETA64 * S;
        }
    }
    __syncthreads();

    const float cin = s_cin[chunk][cloc];
    float pw = beta;
#pragma unroll
    for (int i = 0; i < EMA_L; i++) {
        l2[p0 + (size_t)i * D_] = loc[i] + pw * cin;
        pw *= beta;
    }
}

// ---------------------------------------------------------------------------
// router + fused combine (unchanged)
// ---------------------------------------------------------------------------
__global__ __launch_bounds__(256) void router_fuse(
    const float* __restrict__ hdn, const float* __restrict__ rw2,
    const float* __restrict__ rb2, const float* __restrict__ x,
    const float* __restrict__ l2, const float* __restrict__ l3m,
    float* __restrict__ lam_out, __half* __restrict__ f16)
{
    const int m = blockIdx.x;
    const int tid = threadIdx.x;
    const int HD = D_ / 2;

    const float* hrow = hdn + (size_t)m * HD;
    float s0 = 0.f, s1 = 0.f, s2 = 0.f;
    for (int k = tid; k < HD; k += 256) {
        float hv = hrow[k];
        s0 += hv * rw2[k];
        s1 += hv * rw2[HD + k];
        s2 += hv * rw2[2*HD + k];
    }
#pragma unroll
    for (int o = 16; o > 0; o >>= 1) {
        s0 += __shfl_down_sync(0xffffffffu, s0, o);
        s1 += __shfl_down_sync(0xffffffffu, s1, o);
        s2 += __shfl_down_sync(0xffffffffu, s2, o);
    }
    __shared__ float red[8][3];
    __shared__ float lam_s[3];
    if ((tid & 31) == 0) {
        red[tid >> 5][0] = s0; red[tid >> 5][1] = s1; red[tid >> 5][2] = s2;
    }
    __syncthreads();
    if (tid == 0) {
        float L0 = rb2[0], L1 = rb2[1], L2v = rb2[2];
        for (int w = 0; w < 8; w++) { L0 += red[w][0]; L1 += red[w][1]; L2v += red[w][2]; }
        float mx = fmaxf(L0, fmaxf(L1, L2v));
        float e0 = __expf(L0 - mx), e1 = __expf(L1 - mx), e2 = __expf(L2v - mx);
        float inv = 1.f / (e0 + e1 + e2);
        lam_s[0] = e0 * inv; lam_s[1] = e1 * inv; lam_s[2] = e2 * inv;
        lam_out[m*3+0] = lam_s[0]; lam_out[m*3+1] = lam_s[1]; lam_out[m*3+2] = lam_s[2];
    }
    __syncthreads();
    const float la = lam_s[0], lb = lam_s[1], lc = lam_s[2];
    const int b = m >> 10;
    const float4* xr  = (const float4*)(x  + (size_t)m * D_);
    const float4* l2r = (const float4*)(l2 + (size_t)m * D_);
    const float4* l3r = (const float4*)(l3m + (size_t)b * D_);
    for (int q = tid; q < D_/4; q += 256) {
        float4 xv = xr[q], l2v = l2r[q], l3v = l3r[q];
        float o0 = la*xv.x + lb*l2v.x + lc*l3v.x;
        float o1 = la*xv.y + lb*l2v.y + lc*l3v.y;
        float o2 = la*xv.z + lb*l2v.z + lc*l3v.z;
        float o3 = la*xv.w + lb*l2v.w + lc*l3v.w;
        size_t base = (size_t)m * D_ + q * 4;
        *(__half2*)&f16[base]     = __floats2half2_rn(o0, o1);
        *(__half2*)&f16[base + 2] = __floats2half2_rn(o2, o3);
    }
}

// ---------------------------------------------------------------------------
// tensor-core causal attention (unchanged from R12, proven).
// ---------------------------------------------------------------------------
#define QSTR 136
#define KSTR 136
#define VSTR 72
#define Q_HALVES (128*QSTR)
#define K_HALVES (64*KSTR)
#define V_HALVES (128*VSTR)
#define BUF_HALVES (2*K_HALVES + V_HALVES)
#define ATT_SMEM ((2*Q_HALVES + 2*BUF_HALVES)*2)

__global__ __launch_bounds__(256) void attn_mma_kernel(
    const __half* __restrict__ qh16, const __half* __restrict__ ql16,
    const __half* __restrict__ kh16, const __half* __restrict__ kl16,
    const __half* __restrict__ vt16, __half* __restrict__ o16)
{
    extern __shared__ __half hs[];
    __half* Qh  = hs;
    __half* Ql  = hs + Q_HALVES;
    __half* BUF = hs + 2 * Q_HALVES;

    const int tid  = threadIdx.x;
    const int lane = tid & 31;
    const int w    = tid >> 5;
    const int bh   = blockIdx.y;
    const float scale = 0.08838834764831845f;  // 1/sqrt(128)

    const __half* kbase = kh16 + (size_t)bh * T_ * DH_;
    const __half* lbase = kl16 + (size_t)bh * T_ * DH_;
    const __half* vbase = vt16 + (size_t)bh * DH_ * T_;

#pragma unroll 1
    for (int pass = 0; pass < 2; pass++) {
        const int qb = (pass == 0) ? (int)blockIdx.x : 7 - (int)blockIdx.x;
        const int q0 = qb * 128;
        const int nkt = 2 * qb + 2;

        __syncthreads();

        {
            const int b = bh >> 4, h = bh & 15;
            const __half* qh_g = qh16 + ((size_t)(b * T_ + q0)) * D_ + h * DH_;
            const __half* ql_g = ql16 + ((size_t)(b * T_ + q0)) * D_ + h * DH_;
#pragma unroll
            for (int p = 0; p < 8; p++) {
                int f = p * 256 + tid;
                int r = f >> 4, c = (f & 15) * 8;
                cp_async16(Qh + r * QSTR + c, qh_g + (size_t)r * D_ + c);
                cp_async16(Ql + r * QSTR + c, ql_g + (size_t)r * D_ + c);
            }
        }
        {
            __half* Kd = BUF; __half* Ld = Kd + K_HALVES; __half* Vd = Ld + K_HALVES;
#pragma unroll
            for (int p = 0; p < 4; p++) {
                int f = p * 256 + tid;
                int j = f >> 4, c = (f & 15) * 8;
                cp_async16(Kd + j * KSTR + c, kbase + (size_t)j * DH_ + c);
                cp_async16(Ld + j * KSTR + c, lbase + (size_t)j * DH_ + c);
            }
#pragma unroll
            for (int p = 0; p < 4; p++) {
                int f = p * 256 + tid;
                int dd = f >> 3, c = (f & 7) * 8;
                cp_async16(Vd + dd * VSTR + c, vbase + (size_t)dd * T_ + c);
            }
        }
        CP_COMMIT;

        float m0 = -1e30f, m8 = -1e30f, l0 = 0.f, l8 = 0.f;
        float Oacc[16][4];
#pragma unroll
        for (int nf = 0; nf < 16; nf++)
#pragma unroll
            for (int e = 0; e < 4; e++) Oacc[nf][e] = 0.f;

        const int r0g = q0 + w * 16 + (lane >> 2);
        const int r8g = r0g + 8;

        for (int kt = 0; kt < nkt; kt++) {
            CP_WAIT0;
            __syncthreads();
            if (kt + 1 < nkt) {
                __half* Kd = BUF + ((kt + 1) & 1) * BUF_HALVES;
                __half* Ld = Kd + K_HALVES; __half* Vd = Ld + K_HALVES;
                const __half* kg = kbase + (size_t)(kt + 1) * 64 * DH_;
                const __half* lg = lbase + (size_t)(kt + 1) * 64 * DH_;
                const __half* vg = vbase + (size_t)(kt + 1) * 64;
#pragma unroll
                for (int p = 0; p < 4; p++) {
                    int f = p * 256 + tid;
                    int j = f >> 4, c = (f & 15) * 8;
                    cp_async16(Kd + j * KSTR + c, kg + (size_t)j * DH_ + c);
                    cp_async16(Ld + j * KSTR + c, lg + (size_t)j * DH_ + c);
                }
#pragma unroll
                for (int p = 0; p < 4; p++) {
                    int f = p * 256 + tid;
                    int dd = f >> 3, c = (f & 7) * 8;
                    cp_async16(Vd + dd * VSTR + c, vg + (size_t)dd * T_ + c);
                }
                CP_COMMIT;
            }
            const __half* Kh_ = BUF + (kt & 1) * BUF_HALVES;
            const __half* Kl_ = Kh_ + K_HALVES;
            const __half* Vt_ = Kl_ + K_HALVES;

            float facc[8][4];
#pragma unroll
            for (int nf = 0; nf < 8; nf++)
#pragma unroll
                for (int e = 0; e < 4; e++) facc[nf][e] = 0.f;

#pragma unroll
            for (int ks = 0; ks < 8; ks++) {
                const int ao = (w * 16 + (lane >> 2)) * QSTR + ks * 16 + (lane & 3) * 2;
                unsigned bhf[8][2], blf[8][2];
#pragma unroll
                for (int nf = 0; nf < 8; nf++) {
                    int bo = (nf * 8 + (lane >> 2)) * KSTR + ks * 16 + (lane & 3) * 2;
                    bhf[nf][0] = *(const unsigned*)&Kh_[bo];
                    bhf[nf][1] = *(const unsigned*)&Kh_[bo + 8];
                    blf[nf][0] = *(const unsigned*)&Kl_[bo];
                    blf[nf][1] = *(const unsigned*)&Kl_[bo + 8];
                }
                unsigned af[4];
                af[0] = *(const unsigned*)&Qh[ao];
                af[1] = *(const unsigned*)&Qh[ao + 8 * QSTR];
                af[2] = *(const unsigned*)&Qh[ao + 8];
                af[3] = *(const unsigned*)&Qh[ao + 8 * QSTR + 8];
#pragma unroll
                for (int nf = 0; nf < 8; nf++) mma_fp16(facc[nf], af, bhf[nf]);
#pragma unroll
                for (int nf = 0; nf < 8; nf++) mma_fp16(facc[nf], af, blf[nf]);
                af[0] = *(const unsigned*)&Ql[ao];
                af[1] = *(const unsigned*)&Ql[ao + 8 * QSTR];
                af[2] = *(const unsigned*)&Ql[ao + 8];
                af[3] = *(const unsigned*)&Ql[ao + 8 * QSTR + 8];
#pragma unroll
                for (int nf = 0; nf < 8; nf++) mma_fp16(facc[nf], af, bhf[nf]);
            }

            const int colb = kt * 64 + (lane & 3) * 2;
#pragma unroll
            for (int nf = 0; nf < 8; nf++) {
                int c0 = colb + nf * 8, c1 = c0 + 1;
                float s0 = facc[nf][0] * scale; if (c0 > r0g) s0 = -1e30f;
                float s1 = facc[nf][1] * scale; if (c1 > r0g) s1 = -1e30f;
                float s2 = facc[nf][2] * scale; if (c0 > r8g) s2 = -1e30f;
                float s3 = facc[nf][3] * scale; if (c1 > r8g) s3 = -1e30f;
                facc[nf][0] = s0; facc[nf][1] = s1; facc[nf][2] = s2; facc[nf][3] = s3;
            }

            float mx0 = m0, mx8 = m8;
#pragma unroll
            for (int nf = 0; nf < 8; nf++) {
                mx0 = fmaxf(mx0, fmaxf(facc[nf][0], facc[nf][1]));
                mx8 = fmaxf(mx8, fmaxf(facc[nf][2], facc[nf][3]));
            }
            mx0 = fmaxf(mx0, __shfl_xor_sync(0xffffffffu, mx0, 1));
            mx0 = fmaxf(mx0, __shfl_xor_sync(0xffffffffu, mx0, 2));
            mx8 = fmaxf(mx8, __shfl_xor_sync(0xffffffffu, mx8, 1));
            mx8 = fmaxf(mx8, __shfl_xor_sync(0xffffffffu, mx8, 2));
            float a0 = __expf(m0 - mx0), a8 = __expf(m8 - mx8);
            float ls0 = 0.f, ls8 = 0.f;
#pragma unroll
            for (int nf = 0; nf < 8; nf++) {
                facc[nf][0] = __expf(facc[nf][0] - mx0); ls0 += facc[nf][0];
                facc[nf][1] = __expf(facc[nf][1] - mx0); ls0 += facc[nf][1];
                facc[nf][2] = __expf(facc[nf][2] - mx8); ls8 += facc[nf][2];
                facc[nf][3] = __expf(facc[nf][3] - mx8); ls8 += facc[nf][3];
            }
            ls0 += __shfl_xor_sync(0xffffffffu, ls0, 1);
            ls0 += __shfl_xor_sync(0xffffffffu, ls0, 2);
            ls8 += __shfl_xor_sync(0xffffffffu, ls8, 1);
            ls8 += __shfl_xor_sync(0xffffffffu, ls8, 2);
            m0 = mx0; m8 = mx8;
            l0 = l0 * a0 + ls0;
            l8 = l8 * a8 + ls8;
#pragma unroll
            for (int nf = 0; nf < 16; nf++) {
                Oacc[nf][0] *= a0; Oacc[nf][1] *= a0;
                Oacc[nf][2] *= a8; Oacc[nf][3] *= a8;
            }

#pragma unroll
            for (int kk = 0; kk < 4; kk++) {
                unsigned pa[4];
                pa[0] = packh2(facc[2*kk][0],   facc[2*kk][1]);
                pa[1] = packh2(facc[2*kk][2],   facc[2*kk][3]);
                pa[2] = packh2(facc[2*kk+1][0], facc[2*kk+1][1]);
                pa[3] = packh2(facc[2*kk+1][2], facc[2*kk+1][3]);
#pragma unroll
                for (int nf = 0; nf < 16; nf++) {
                    int vo = (nf * 8 + (lane >> 2)) * VSTR + kk * 16 + (lane & 3) * 2;
                    unsigned vb[2];
                    vb[0] = *(const unsigned*)&Vt_[vo];
                    vb[1] = *(const unsigned*)&Vt_[vo + 8];
                    mma_fp16(Oacc[nf], pa, vb);
                }
            }
        }

        const float i0 = 1.f / l0, i8 = 1.f / l8;
        const int b = bh >> 4, h = bh & 15;
        size_t row0 = ((size_t)(b * T_ + q0 + w * 16 + (lane >> 2))) * D_
                    + h * DH_ + (lane & 3) * 2;
#pragma unroll
        for (int nf = 0; nf < 16; nf++) {
            *(__half2*)&o16[row0 + nf * 8] =
                __floats2half2_rn(Oacc[nf][0] * i0, Oacc[nf][1] * i0);
            *(__half2*)&o16[row0 + 8 * D_ + nf * 8] =
                __floats2half2_rn(Oacc[nf][2] * i8, Oacc[nf][3] * i8);
        }
    }
}

// ---------------------------------------------------------------------------
extern "C" void kernel_launch(void* const* d_in, const int* in_sizes, int n_in,
                              void* d_out, int out_size)
{
    const float* x   = (const float*)d_in[0];
    const float* l3m = (const float*)d_in[1];
    const float* wq  = (const float*)d_in[2];
    const float* wk  = (const float*)d_in[3];
    const float* wv  = (const float*)d_in[4];
    const float* wo  = (const float*)d_in[5];
    const float* rw1 = (const float*)d_in[6];
    const float* rb1 = (const float*)d_in[7];
    const float* rw2 = (const float*)d_in[8];
    const float* rb2 = (const float*)d_in[9];

    float* out  = (float*)d_out;
    float* khp  = out + (size_t)NELEM;
    float* vhp  = khp + (size_t)NELEM;
    float* lamp = vhp + (size_t)NELEM;

    float *l2s, *hdns;
    cudaGetSymbolAddress((void**)&l2s,  g_l2);
    cudaGetSymbolAddress((void**)&hdns, g_hdn);
    __half *x16,*wq16,*wk16,*wv16,*wo16,*r116,*qh,*ql,*f16,*kh,*kl,*vt,*a16;
    cudaGetSymbolAddress((void**)&x16,  g_x16);
    cudaGetSymbolAddress((void**)&wq16, g_wq16);
    cudaGetSymbolAddress((void**)&wk16, g_wk16);
    cudaGetSymbolAddress((void**)&wv16, g_wv16);
    cudaGetSymbolAddress((void**)&wo16, g_wo16);
    cudaGetSymbolAddress((void**)&r116, g_rw116);
    cudaGetSymbolAddress((void**)&qh,   g_qh16);
    cudaGetSymbolAddress((void**)&ql,   g_ql16);
    cudaGetSymbolAddress((void**)&f16,  g_f16);
    cudaGetSymbolAddress((void**)&kh,   g_kh16);
    cudaGetSymbolAddress((void**)&kl,   g_kl16);
    cudaGetSymbolAddress((void**)&vt,   g_vt16);
    cudaGetSymbolAddress((void**)&a16,  g_a16);

    dim3 blk(256);

    cudaFuncSetAttribute(mma_gemm_tn<0,0,2>, cudaFuncAttributeMaxDynamicSharedMemorySize, GEMM_SMEM);
    cudaFuncSetAttribute(mma_gemm_tn<0,0,0>, cudaFuncAttributeMaxDynamicSharedMemorySize, GEMM_SMEM);
    cudaFuncSetAttribute(mma_gemm_tn<0,1,0>, cudaFuncAttributeMaxDynamicSharedMemorySize, GEMM_SMEM);
    cudaFuncSetAttribute(mma_gemm_tn<1,0,3>, cudaFuncAttributeMaxDynamicSharedMemorySize, GEMM_SMEM);
    cudaFuncSetAttribute(attn_mma_kernel, cudaFuncAttributeMaxDynamicSharedMemorySize, ATT_SMEM);

    // 1-3, then q-GEMM at slot #4 (ncu capture slot)
    cvt_kernel<<<NELEM/1024, 256>>>(x,   x16,  NELEM);
    cvt_kernel<<<(D_*D_)/1024, 256>>>(wq, wq16, D_*D_);
    ema_scan_kernel<<<(B_*D_)/16, 256>>>(x, l2s);
    // q = x @ wq^T -> fp16 hi/lo only
    mma_gemm_tn<0,0,2><<<dim3(D_/128, MROWS/128), blk, GEMM_SMEM>>>(
        x16, wq16, nullptr, nullptr, nullptr, nullptr, qh, ql, nullptr, MROWS, D_, D_);

    cvt3_kernel<<<dim3((D_*D_)/1024, 3), 256>>>(wk, wk16, wv, wv16, wo, wo16, D_*D_);
    cvt_kernel<<<((D_/2)*D_)/1024, 256>>>(rw1, r116, (D_/2)*D_);

    // hdn = silu(q @ rw1^T + rb1)   (uses q hi fp16)
    mma_gemm_tn<0,1,0><<<dim3((D_/2)/128, MROWS/128), blk, GEMM_SMEM>>>(
        qh, r116, nullptr, rb1, hdns, nullptr, nullptr, nullptr, nullptr, MROWS, D_/2, D_);
    // lam + fused (fp16)
    router_fuse<<<MROWS, 256>>>(hdns, rw2, rb2, x, l2s, l3m, lamp, f16);
    // kh + vh in one launch; z=0 also emits K hi/lo fp16, z=1 emits V^T fp16
    mma_gemm_tn<1,0,3><<<dim3(D_/128, MROWS/128, 2), blk, GEMM_SMEM>>>(
        f16, wk16, wv16, nullptr, khp, vhp, kh, kl, vt, MROWS, D_, D_);
    // tensor-core attention: paired q-blocks {i, 7-i}, grid (4, 32)
    attn_mma_kernel<<<dim3(4, B_*H_), blk, ATT_SMEM>>>(qh, ql, kh, kl, vt, a16);
    // out = attn @ wo^T
    mma_gemm_tn<0,0,0><<<dim3(D_/128, MROWS/128), blk, GEMM_SMEM>>>(
        a16, wo16, nullptr, nullptr, out, nullptr, nullptr, nullptr, nullptr, MROWS, D_, D_);
}

// round 15
// speedup vs baseline: 2.4502x; 1.0334x over previous
#include <cuda_runtime.h>
#include <cuda_fp16.h>
#include <math.h>
#include <stdint.h>

// ---------------------------------------------------------------------------
// FastMKAAttention — round 14: 4-stage cp.async pipeline in the GEMM mainloop
// (R13 ldmatrix fragment path + attention unchanged)
// shapes: b=2, t=1024, d=2048, h=16, dh=128
// output tuple (floats): out[4194304] | kh[4194304] | vh[4194304] | lam[6144]
// ---------------------------------------------------------------------------

#define B_   2
#define T_   1024
#define D_   2048
#define H_   16
#define DH_  128
#define MROWS (B_*T_)          // 2048
#define NELEM (B_*T_*D_)       // 4194304

// fp32 scratch
__device__ float g_l2[NELEM];           // EMA
__device__ float g_hdn[MROWS*(D_/2)];   // router hidden

// fp16 scratch
__device__ __half g_x16[NELEM];
__device__ __half g_wq16[D_*D_];
__device__ __half g_wk16[D_*D_];
__device__ __half g_wv16[D_*D_];
__device__ __half g_wo16[D_*D_];
__device__ __half g_rw116[(D_/2)*D_];
__device__ __half g_qh16[NELEM];        // q hi (also feeds router GEMM)
__device__ __half g_ql16[NELEM];        // q lo
__device__ __half g_f16[NELEM];         // fused (fp16)
__device__ __half g_kh16[NELEM];        // K hi  [b,h,t,dh]
__device__ __half g_kl16[NELEM];        // K lo  [b,h,t,dh]
__device__ __half g_vt16[NELEM];        // V fp16 transposed [b,h,dh,t]
__device__ __half g_a16[NELEM];         // attention out (fp16)

// ---------------------------------------------------------------------------
// helpers
// ---------------------------------------------------------------------------
__device__ __forceinline__ void cp_async16(void* dst, const void* src) {
    unsigned s = (unsigned)__cvta_generic_to_shared(dst);
    asm volatile("cp.async.cg.shared.global [%0], [%1], 16;" :: "r"(s), "l"(src));
}
#define CP_COMMIT asm volatile("cp.async.commit_group;")
#define CP_WAIT0  asm volatile("cp.async.wait_group 0;")
#define CP_WAIT2  asm volatile("cp.async.wait_group 2;")

__device__ __forceinline__ void mma_fp16(float* c, const unsigned* a, const unsigned* b) {
    asm volatile(
        "mma.sync.aligned.m16n8k16.row.col.f32.f16.f16.f32 "
        "{%0,%1,%2,%3}, {%4,%5,%6,%7}, {%8,%9}, {%0,%1,%2,%3};\n"
        : "+f"(c[0]), "+f"(c[1]), "+f"(c[2]), "+f"(c[3])
        : "r"(a[0]), "r"(a[1]), "r"(a[2]), "r"(a[3]), "r"(b[0]), "r"(b[1]));
}

__device__ __forceinline__ void ldsm_x4(unsigned* r, unsigned addr) {
    asm volatile("ldmatrix.sync.aligned.m8n8.x4.shared.b16 {%0,%1,%2,%3}, [%4];"
                 : "=r"(r[0]), "=r"(r[1]), "=r"(r[2]), "=r"(r[3]) : "r"(addr));
}

__device__ __forceinline__ unsigned packh2(float a, float b) {
    __half2 h = __floats2half2_rn(a, b);
    return *(unsigned*)&h;
}

// ---------------------------------------------------------------------------
// convert kernels: fp32 -> fp16
// ---------------------------------------------------------------------------
__global__ void cvt_kernel(const float* __restrict__ src,
                           __half* __restrict__ dst, int n)
{
    int i = (blockIdx.x * blockDim.x + threadIdx.x) * 4;
    if (i >= n) return;
    float4 v = *(const float4*)(src + i);
    *(__half2*)(dst + i)     = __floats2half2_rn(v.x, v.y);
    *(__half2*)(dst + i + 2) = __floats2half2_rn(v.z, v.w);
}

__global__ void cvt3_kernel(const float* __restrict__ s0, __half* __restrict__ d0,
                            const float* __restrict__ s1, __half* __restrict__ d1,
                            const float* __restrict__ s2, __half* __restrict__ d2,
                            int n)
{
    const float* src = (blockIdx.y == 0) ? s0 : (blockIdx.y == 1) ? s1 : s2;
    __half* dst      = (blockIdx.y == 0) ? d0 : (blockIdx.y == 1) ? d1 : d2;
    int i = (blockIdx.x * blockDim.x + threadIdx.x) * 4;
    if (i >= n) return;
    float4 v = *(const float4*)(src + i);
    *(__half2*)(dst + i)     = __floats2half2_rn(v.x, v.y);
    *(__half2*)(dst + i + 2) = __floats2half2_rn(v.z, v.w);
}

// ---------------------------------------------------------------------------
// fp16 mma GEMM: ldmatrix fragments + 4-stage cp.async pipeline.
// MODE 0: row-major. MODE 1: scatter [b,h,t,dh]; grid.z selects wk/wv.
// F16OUT: 0 none; 2 = write ONLY fp16 hi/lo (C16/C16b), skip fp32;
//         3 = MODE1 extras: z=0 -> kh16/kl16 (C16/C16b); z=1 -> vt16 (C16c).
// ---------------------------------------------------------------------------
#define SSTR 40
#define HELEMS (128*SSTR)
#define STAGE_ELEMS (2*HELEMS)
#define STAGE_BYTES (STAGE_ELEMS*2)
#define GEMM_SMEM (4*STAGE_BYTES)     // 81920 B (4 stages)
#define ASTEP_B (16*SSTR*2)
#define BSTEP_B (16*SSTR*2)

__device__ __forceinline__ void stage_tile(
    const __half* __restrict__ A, const __half* __restrict__ Bm,
    __half* sbuf, int bm, int bn, int kt, int K, int tid)
{
    const __half* ga = A  + (size_t)bm * K + kt;
    const __half* gb = Bm + (size_t)bn * K + kt;
#pragma unroll
    for (int p = 0; p < 2; p++) {
        int idx = p * 256 + tid;
        int row = idx >> 2;
        int c8  = (idx & 3) * 8;
        cp_async16(sbuf + row * SSTR + c8,          ga + (size_t)row * K + c8);
        cp_async16(sbuf + HELEMS + row * SSTR + c8, gb + (size_t)row * K + c8);
    }
}

template<int MODE, int ACT, int F16OUT>
__global__ __launch_bounds__(256) void mma_gemm_tn(
    const __half* __restrict__ A, const __half* __restrict__ Bm,
    const __half* __restrict__ Bm2,
    const float* __restrict__ bias, float* __restrict__ C, float* __restrict__ C2,
    __half* __restrict__ C16, __half* __restrict__ C16b, __half* __restrict__ C16c,
    int M, int N, int K)
{
    extern __shared__ __half smem[];
    const unsigned smem_u32 = (unsigned)__cvta_generic_to_shared(smem);

    const __half* Bsel = (blockIdx.z == 1) ? Bm2 : Bm;
    float*        Csel = (blockIdx.z == 1) ? C2  : C;

    const int tid  = threadIdx.x;
    const int lane = tid & 31;
    const int wid  = tid >> 5;
    const int wm   = wid >> 2;
    const int wn   = wid & 3;
    const int bm   = blockIdx.y * 128;
    const int bn   = blockIdx.x * 128;

    // ldmatrix per-lane byte offsets within a half-tile
    const unsigned a_off = ((wm * 64 + (lane & 15)) * SSTR + (lane >> 4) * 8) * 2;
    const unsigned b_off = ((wn * 32 + (lane & 7) + ((lane >> 4) << 3)) * SSTR
                            + ((lane >> 3) & 1) * 8) * 2;

    float acc[4][4][4];
#pragma unroll
    for (int i = 0; i < 4; i++)
#pragma unroll
        for (int j = 0; j < 4; j++)
#pragma unroll
            for (int r = 0; r < 4; r++) acc[i][j][r] = 0.f;

    const int nt = K / 32;
    // prologue: stage tiles 0..2
#pragma unroll
    for (int s = 0; s < 3; s++) {
        if (s < nt) {
            stage_tile(A, Bsel, smem + s * STAGE_ELEMS, bm, bn, s * 32, K, tid);
        }
        CP_COMMIT;
    }

    for (int it = 0; it < nt; it++) {
        CP_WAIT2;            // with the always-commit invariant, tile `it` is resident
        __syncthreads();     // all warps done with buffer (it-1)&3; data visible
        if (it + 3 < nt) {
            stage_tile(A, Bsel, smem + ((it + 3) & 3) * STAGE_ELEMS,
                       bm, bn, (it + 3) * 32, K, tid);
        }
        CP_COMMIT;           // always commit (possibly empty group at tail)

        const unsigned base   = smem_u32 + (it & 3) * STAGE_BYTES;
        const unsigned a_base = base + a_off;
        const unsigned b_base = base + HELEMS * 2 + b_off;

#pragma unroll
        for (int ks = 0; ks < 2; ks++) {
            const unsigned ko = ks * 32;   // 16 halves = 32 bytes
            unsigned af[4][4];
#pragma unroll
            for (int mf = 0; mf < 4; mf++)
                ldsm_x4(af[mf], a_base + mf * ASTEP_B + ko);
            unsigned bq[2][4];
            ldsm_x4(bq[0], b_base + ko);
            ldsm_x4(bq[1], b_base + BSTEP_B + ko);
#pragma unroll
            for (int mf = 0; mf < 4; mf++)
#pragma unroll
                for (int nf = 0; nf < 4; nf++) {
                    unsigned bfr[2];
                    bfr[0] = bq[nf >> 1][(nf & 1) * 2 + 0];
                    bfr[1] = bq[nf >> 1][(nf & 1) * 2 + 1];
                    mma_fp16(acc[mf][nf], af[mf], bfr);
                }
        }
    }

    // epilogue
#pragma unroll
    for (int mf = 0; mf < 4; mf++) {
#pragma unroll
        for (int nf = 0; nf < 4; nf++) {
            int m0 = bm + wm * 64 + mf * 16 + (lane >> 2);
            int n  = bn + wn * 32 + nf * 8 + (lane & 3) * 2;
#pragma unroll
            for (int half = 0; half < 2; half++) {
                int m = m0 + half * 8;
                float2 v;
                v.x = acc[mf][nf][half * 2 + 0];
                v.y = acc[mf][nf][half * 2 + 1];
                if (ACT == 1) {
                    v.x += bias[n];
                    v.y += bias[n + 1];
                    v.x = v.x / (1.f + __expf(-v.x));
                    v.y = v.y / (1.f + __expf(-v.y));
                }
                if (MODE == 0) {
                    size_t idx = (size_t)m * N + n;
                    if (F16OUT == 2) {
                        __half2 hh = __floats2half2_rn(v.x, v.y);
                        *(__half2*)&C16[idx] = hh;
                        float lx = v.x - __half2float(__low2half(hh));
                        float ly = v.y - __half2float(__high2half(hh));
                        *(__half2*)&C16b[idx] = __floats2half2_rn(lx, ly);
                    } else {
                        if (C) *(float2*)&C[idx] = v;
                        if (F16OUT == 1)
                            *(__half2*)&C16[idx] = __floats2half2_rn(v.x, v.y);
                    }
                } else {
                    size_t idx = (size_t)(m >> 10) * (H_*T_*DH_) + (size_t)(n >> 7) * (T_*DH_)
                               + (size_t)(m & 1023) * DH_ + (n & 127);
                    *(float2*)&Csel[idx] = v;
                    if (F16OUT == 3) {
                        if (blockIdx.z == 0) {
                            __half2 hh = __floats2half2_rn(v.x, v.y);
                            *(__half2*)&C16[idx] = hh;
                            float lx = v.x - __half2float(__low2half(hh));
                            float ly = v.y - __half2float(__high2half(hh));
                            *(__half2*)&C16b[idx] = __floats2half2_rn(lx, ly);
                        } else {
                            size_t tb = ((size_t)((m >> 10) * H_ + (n >> 7)) * DH_
                                         + (n & 127)) * T_ + (m & 1023);
                            C16c[tb]      = __float2half(v.x);
                            C16c[tb + T_] = __float2half(v.y);
                        }
                    }
                }
            }
        }
    }
}

// ---------------------------------------------------------------------------
// causal EMA — parallel scan (unchanged)
// ---------------------------------------------------------------------------
#define EMA_L  64
#define EMA_NC 16
#define BETA64 1.1790184577738583e-3f   // 0.9^64

__global__ __launch_bounds__(256) void ema_scan_kernel(
    const float* __restrict__ x, float* __restrict__ l2)
{
    __shared__ float s_end[EMA_NC][17];
    __shared__ float s_cin[EMA_NC][17];

    const int tid   = threadIdx.x;
    const int cloc  = tid & 15;
    const int chunk = tid >> 4;
    const int ch    = blockIdx.x * 16 + cloc;
    const int b     = ch >> 11;
    const int d     = ch & (D_ - 1);

    const float beta = 0.9f, omb = 0.1f;
    const size_t base = (size_t)b * T_ * D_ + d;
    const size_t p0   = base + (size_t)chunk * EMA_L * D_;

    float loc[EMA_L];
    float s = 0.f;
#pragma unroll
    for (int i = 0; i < EMA_L; i++) {
        s = beta * s + omb * x[p0 + (size_t)i * D_];
        loc[i] = s;
    }
    s_end[chunk][cloc] = s;
    __syncthreads();

    if (chunk == 0) {
        float S = 0.f;
#pragma unroll
        for (int k = 0; k < EMA_NC; k++) {
            s_cin[k][cloc] = S;
            S = s_end[k][cloc] + BETA64 * S;
        }
    }
    __syncthreads();

    const float cin = s_cin[chunk][cloc];
    float pw = beta;
#pragma unroll
    for (int i = 0; i < EMA_L; i++) {
        l2[p0 + (size_t)i * D_] = loc[i] + pw * cin;
        pw *= beta;
    }
}

// ---------------------------------------------------------------------------
// router + fused combine (unchanged)
// ---------------------------------------------------------------------------
__global__ __launch_bounds__(256) void router_fuse(
    const float* __restrict__ hdn, const float* __restrict__ rw2,
    const float* __restrict__ rb2, const float* __restrict__ x,
    const float* __restrict__ l2, const float* __restrict__ l3m,
    float* __restrict__ lam_out, __half* __restrict__ f16)
{
    const int m = blockIdx.x;
    const int tid = threadIdx.x;
    const int HD = D_ / 2;

    const float* hrow = hdn + (size_t)m * HD;
    float s0 = 0.f, s1 = 0.f, s2 = 0.f;
    for (int k = tid; k < HD; k += 256) {
        float hv = hrow[k];
        s0 += hv * rw2[k];
        s1 += hv * rw2[HD + k];
        s2 += hv * rw2[2*HD + k];
    }
#pragma unroll
    for (int o = 16; o > 0; o >>= 1) {
        s0 += __shfl_down_sync(0xffffffffu, s0, o);
        s1 += __shfl_down_sync(0xffffffffu, s1, o);
        s2 += __shfl_down_sync(0xffffffffu, s2, o);
    }
    __shared__ float red[8][3];
    __shared__ float lam_s[3];
    if ((tid & 31) == 0) {
        red[tid >> 5][0] = s0; red[tid >> 5][1] = s1; red[tid >> 5][2] = s2;
    }
    __syncthreads();
    if (tid == 0) {
        float L0 = rb2[0], L1 = rb2[1], L2v = rb2[2];
        for (int w = 0; w < 8; w++) { L0 += red[w][0]; L1 += red[w][1]; L2v += red[w][2]; }
        float mx = fmaxf(L0, fmaxf(L1, L2v));
        float e0 = __expf(L0 - mx), e1 = __expf(L1 - mx), e2 = __expf(L2v - mx);
        float inv = 1.f / (e0 + e1 + e2);
        lam_s[0] = e0 * inv; lam_s[1] = e1 * inv; lam_s[2] = e2 * inv;
        lam_out[m*3+0] = lam_s[0]; lam_out[m*3+1] = lam_s[1]; lam_out[m*3+2] = lam_s[2];
    }
    __syncthreads();
    const float la = lam_s[0], lb = lam_s[1], lc = lam_s[2];
    const int b = m >> 10;
    const float4* xr  = (const float4*)(x  + (size_t)m * D_);
    const float4* l2r = (const float4*)(l2 + (size_t)m * D_);
    const float4* l3r = (const float4*)(l3m + (size_t)b * D_);
    for (int q = tid; q < D_/4; q += 256) {
        float4 xv = xr[q], l2v = l2r[q], l3v = l3r[q];
        float o0 = la*xv.x + lb*l2v.x + lc*l3v.x;
        float o1 = la*xv.y + lb*l2v.y + lc*l3v.y;
        float o2 = la*xv.z + lb*l2v.z + lc*l3v.z;
        float o3 = la*xv.w + lb*l2v.w + lc*l3v.w;
        size_t base = (size_t)m * D_ + q * 4;
        *(__half2*)&f16[base]     = __floats2half2_rn(o0, o1);
        *(__half2*)&f16[base + 2] = __floats2half2_rn(o2, o3);
    }
}

// ---------------------------------------------------------------------------
// tensor-core causal attention (unchanged from R12/R13, proven).
// ---------------------------------------------------------------------------
#define QSTR 136
#define KSTR 136
#define VSTR 72
#define Q_HALVES (128*QSTR)
#define K_HALVES (64*KSTR)
#define V_HALVES (128*VSTR)
#define BUF_HALVES (2*K_HALVES + V_HALVES)
#define ATT_SMEM ((2*Q_HALVES + 2*BUF_HALVES)*2)

__global__ __launch_bounds__(256) void attn_mma_kernel(
    const __half* __restrict__ qh16, const __half* __restrict__ ql16,
    const __half* __restrict__ kh16, const __half* __restrict__ kl16,
    const __half* __restrict__ vt16, __half* __restrict__ o16)
{
    extern __shared__ __half hs[];
    __half* Qh  = hs;
    __half* Ql  = hs + Q_HALVES;
    __half* BUF = hs + 2 * Q_HALVES;

    const int tid  = threadIdx.x;
    const int lane = tid & 31;
    const int w    = tid >> 5;
    const int bh   = blockIdx.y;
    const float scale = 0.08838834764831845f;  // 1/sqrt(128)

    const __half* kbase = kh16 + (size_t)bh * T_ * DH_;
    const __half* lbase = kl16 + (size_t)bh * T_ * DH_;
    const __half* vbase = vt16 + (size_t)bh * DH_ * T_;

#pragma unroll 1
    for (int pass = 0; pass < 2; pass++) {
        const int qb = (pass == 0) ? (int)blockIdx.x : 7 - (int)blockIdx.x;
        const int q0 = qb * 128;
        const int nkt = 2 * qb + 2;

        __syncthreads();

        {
            const int b = bh >> 4, h = bh & 15;
            const __half* qh_g = qh16 + ((size_t)(b * T_ + q0)) * D_ + h * DH_;
            const __half* ql_g = ql16 + ((size_t)(b * T_ + q0)) * D_ + h * DH_;
#pragma unroll
            for (int p = 0; p < 8; p++) {
                int f = p * 256 + tid;
                int r = f >> 4, c = (f & 15) * 8;
                cp_async16(Qh + r * QSTR + c, qh_g + (size_t)r * D_ + c);
                cp_async16(Ql + r * QSTR + c, ql_g + (size_t)r * D_ + c);
            }
        }
        {
            __half* Kd = BUF; __half* Ld = Kd + K_HALVES; __half* Vd = Ld + K_HALVES;
#pragma unroll
            for (int p = 0; p < 4; p++) {
                int f = p * 256 + tid;
                int j = f >> 4, c = (f & 15) * 8;
                cp_async16(Kd + j * KSTR + c, kbase + (size_t)j * DH_ + c);
                cp_async16(Ld + j * KSTR + c, lbase + (size_t)j * DH_ + c);
            }
#pragma unroll
            for (int p = 0; p < 4; p++) {
                int f = p * 256 + tid;
                int dd = f >> 3, c = (f & 7) * 8;
                cp_async16(Vd + dd * VSTR + c, vbase + (size_t)dd * T_ + c);
            }
        }
        CP_COMMIT;

        float m0 = -1e30f, m8 = -1e30f, l0 = 0.f, l8 = 0.f;
        float Oacc[16][4];
#pragma unroll
        for (int nf = 0; nf < 16; nf++)
#pragma unroll
            for (int e = 0; e < 4; e++) Oacc[nf][e] = 0.f;

        const int r0g = q0 + w * 16 + (lane >> 2);
        const int r8g = r0g + 8;

        for (int kt = 0; kt < nkt; kt++) {
            CP_WAIT0;
            __syncthreads();
            if (kt + 1 < nkt) {
                __half* Kd = BUF + ((kt + 1) & 1) * BUF_HALVES;
                __half* Ld = Kd + K_HALVES; __half* Vd = Ld + K_HALVES;
                const __half* kg = kbase + (size_t)(kt + 1) * 64 * DH_;
                const __half* lg = lbase + (size_t)(kt + 1) * 64 * DH_;
                const __half* vg = vbase + (size_t)(kt + 1) * 64;
#pragma unroll
                for (int p = 0; p < 4; p++) {
                    int f = p * 256 + tid;
                    int j = f >> 4, c = (f & 15) * 8;
                    cp_async16(Kd + j * KSTR + c, kg + (size_t)j * DH_ + c);
                    cp_async16(Ld + j * KSTR + c, lg + (size_t)j * DH_ + c);
                }
#pragma unroll
                for (int p = 0; p < 4; p++) {
                    int f = p * 256 + tid;
                    int dd = f >> 3, c = (f & 7) * 8;
                    cp_async16(Vd + dd * VSTR + c, vg + (size_t)dd * T_ + c);
                }
                CP_COMMIT;
            }
            const __half* Kh_ = BUF + (kt & 1) * BUF_HALVES;
            const __half* Kl_ = Kh_ + K_HALVES;
            const __half* Vt_ = Kl_ + K_HALVES;

            float facc[8][4];
#pragma unroll
            for (int nf = 0; nf < 8; nf++)
#pragma unroll
                for (int e = 0; e < 4; e++) facc[nf][e] = 0.f;

#pragma unroll
            for (int ks = 0; ks < 8; ks++) {
                const int ao = (w * 16 + (lane >> 2)) * QSTR + ks * 16 + (lane & 3) * 2;
                unsigned bhf[8][2], blf[8][2];
#pragma unroll
                for (int nf = 0; nf < 8; nf++) {
                    int bo = (nf * 8 + (lane >> 2)) * KSTR + ks * 16 + (lane & 3) * 2;
                    bhf[nf][0] = *(const unsigned*)&Kh_[bo];
                    bhf[nf][1] = *(const unsigned*)&Kh_[bo + 8];
                    blf[nf][0] = *(const unsigned*)&Kl_[bo];
                    blf[nf][1] = *(const unsigned*)&Kl_[bo + 8];
                }
                unsigned af[4];
                af[0] = *(const unsigned*)&Qh[ao];
                af[1] = *(const unsigned*)&Qh[ao + 8 * QSTR];
                af[2] = *(const unsigned*)&Qh[ao + 8];
                af[3] = *(const unsigned*)&Qh[ao + 8 * QSTR + 8];
#pragma unroll
                for (int nf = 0; nf < 8; nf++) mma_fp16(facc[nf], af, bhf[nf]);
#pragma unroll
                for (int nf = 0; nf < 8; nf++) mma_fp16(facc[nf], af, blf[nf]);
                af[0] = *(const unsigned*)&Ql[ao];
                af[1] = *(const unsigned*)&Ql[ao + 8 * QSTR];
                af[2] = *(const unsigned*)&Ql[ao + 8];
                af[3] = *(const unsigned*)&Ql[ao + 8 * QSTR + 8];
#pragma unroll
                for (int nf = 0; nf < 8; nf++) mma_fp16(facc[nf], af, bhf[nf]);
            }

            const int colb = kt * 64 + (lane & 3) * 2;
#pragma unroll
            for (int nf = 0; nf < 8; nf++) {
                int c0 = colb + nf * 8, c1 = c0 + 1;
                float s0 = facc[nf][0] * scale; if (c0 > r0g) s0 = -1e30f;
                float s1 = facc[nf][1] * scale; if (c1 > r0g) s1 = -1e30f;
                float s2 = facc[nf][2] * scale; if (c0 > r8g) s2 = -1e30f;
                float s3 = facc[nf][3] * scale; if (c1 > r8g) s3 = -1e30f;
                facc[nf][0] = s0; facc[nf][1] = s1; facc[nf][2] = s2; facc[nf][3] = s3;
            }

            float mx0 = m0, mx8 = m8;
#pragma unroll
            for (int nf = 0; nf < 8; nf++) {
                mx0 = fmaxf(mx0, fmaxf(facc[nf][0], facc[nf][1]));
                mx8 = fmaxf(mx8, fmaxf(facc[nf][2], facc[nf][3]));
            }
            mx0 = fmaxf(mx0, __shfl_xor_sync(0xffffffffu, mx0, 1));
            mx0 = fmaxf(mx0, __shfl_xor_sync(0xffffffffu, mx0, 2));
            mx8 = fmaxf(mx8, __shfl_xor_sync(0xffffffffu, mx8, 1));
            mx8 = fmaxf(mx8, __shfl_xor_sync(0xffffffffu, mx8, 2));
            float a0 = __expf(m0 - mx0), a8 = __expf(m8 - mx8);
            float ls0 = 0.f, ls8 = 0.f;
#pragma unroll
            for (int nf = 0; nf < 8; nf++) {
                facc[nf][0] = __expf(facc[nf][0] - mx0); ls0 += facc[nf][0];
                facc[nf][1] = __expf(facc[nf][1] - mx0); ls0 += facc[nf][1];
                facc[nf][2] = __expf(facc[nf][2] - mx8); ls8 += facc[nf][2];
                facc[nf][3] = __expf(facc[nf][3] - mx8); ls8 += facc[nf][3];
            }
            ls0 += __shfl_xor_sync(0xffffffffu, ls0, 1);
            ls0 += __shfl_xor_sync(0xffffffffu, ls0, 2);
            ls8 += __shfl_xor_sync(0xffffffffu, ls8, 1);
            ls8 += __shfl_xor_sync(0xffffffffu, ls8, 2);
            m0 = mx0; m8 = mx8;
            l0 = l0 * a0 + ls0;
            l8 = l8 * a8 + ls8;
#pragma unroll
            for (int nf = 0; nf < 16; nf++) {
                Oacc[nf][0] *= a0; Oacc[nf][1] *= a0;
                Oacc[nf][2] *= a8; Oacc[nf][3] *= a8;
            }

#pragma unroll
            for (int kk = 0; kk < 4; kk++) {
                unsigned pa[4];
                pa[0] = packh2(facc[2*kk][0],   facc[2*kk][1]);
                pa[1] = packh2(facc[2*kk][2],   facc[2*kk][3]);
                pa[2] = packh2(facc[2*kk+1][0], facc[2*kk+1][1]);
                pa[3] = packh2(facc[2*kk+1][2], facc[2*kk+1][3]);
#pragma unroll
                for (int nf = 0; nf < 16; nf++) {
                    int vo = (nf * 8 + (lane >> 2)) * VSTR + kk * 16 + (lane & 3) * 2;
                    unsigned vb[2];
                    vb[0] = *(const unsigned*)&Vt_[vo];
                    vb[1] = *(const unsigned*)&Vt_[vo + 8];
                    mma_fp16(Oacc[nf], pa, vb);
                }
            }
        }

        const float i0 = 1.f / l0, i8 = 1.f / l8;
        const int b = bh >> 4, h = bh & 15;
        size_t row0 = ((size_t)(b * T_ + q0 + w * 16 + (lane >> 2))) * D_
                    + h * DH_ + (lane & 3) * 2;
#pragma unroll
        for (int nf = 0; nf < 16; nf++) {
            *(__half2*)&o16[row0 + nf * 8] =
                __floats2half2_rn(Oacc[nf][0] * i0, Oacc[nf][1] * i0);
            *(__half2*)&o16[row0 + 8 * D_ + nf * 8] =
                __floats2half2_rn(Oacc[nf][2] * i8, Oacc[nf][3] * i8);
        }
    }
}

// ---------------------------------------------------------------------------
extern "C" void kernel_launch(void* const* d_in, const int* in_sizes, int n_in,
                              void* d_out, int out_size)
{
    const float* x   = (const float*)d_in[0];
    const float* l3m = (const float*)d_in[1];
    const float* wq  = (const float*)d_in[2];
    const float* wk  = (const float*)d_in[3];
    const float* wv  = (const float*)d_in[4];
    const float* wo  = (const float*)d_in[5];
    const float* rw1 = (const float*)d_in[6];
    const float* rb1 = (const float*)d_in[7];
    const float* rw2 = (const float*)d_in[8];
    const float* rb2 = (const float*)d_in[9];

    float* out  = (float*)d_out;
    float* khp  = out + (size_t)NELEM;
    float* vhp  = khp + (size_t)NELEM;
    float* lamp = vhp + (size_t)NELEM;

    float *l2s, *hdns;
    cudaGetSymbolAddress((void**)&l2s,  g_l2);
    cudaGetSymbolAddress((void**)&hdns, g_hdn);
    __half *x16,*wq16,*wk16,*wv16,*wo16,*r116,*qh,*ql,*f16,*kh,*kl,*vt,*a16;
    cudaGetSymbolAddress((void**)&x16,  g_x16);
    cudaGetSymbolAddress((void**)&wq16, g_wq16);
    cudaGetSymbolAddress((void**)&wk16, g_wk16);
    cudaGetSymbolAddress((void**)&wv16, g_wv16);
    cudaGetSymbolAddress((void**)&wo16, g_wo16);
    cudaGetSymbolAddress((void**)&r116, g_rw116);
    cudaGetSymbolAddress((void**)&qh,   g_qh16);
    cudaGetSymbolAddress((void**)&ql,   g_ql16);
    cudaGetSymbolAddress((void**)&f16,  g_f16);
    cudaGetSymbolAddress((void**)&kh,   g_kh16);
    cudaGetSymbolAddress((void**)&kl,   g_kl16);
    cudaGetSymbolAddress((void**)&vt,   g_vt16);
    cudaGetSymbolAddress((void**)&a16,  g_a16);

    dim3 blk(256);

    cudaFuncSetAttribute(mma_gemm_tn<0,0,2>, cudaFuncAttributeMaxDynamicSharedMemorySize, GEMM_SMEM);
    cudaFuncSetAttribute(mma_gemm_tn<0,0,0>, cudaFuncAttributeMaxDynamicSharedMemorySize, GEMM_SMEM);
    cudaFuncSetAttribute(mma_gemm_tn<0,1,0>, cudaFuncAttributeMaxDynamicSharedMemorySize, GEMM_SMEM);
    cudaFuncSetAttribute(mma_gemm_tn<1,0,3>, cudaFuncAttributeMaxDynamicSharedMemorySize, GEMM_SMEM);
    cudaFuncSetAttribute(attn_mma_kernel, cudaFuncAttributeMaxDynamicSharedMemorySize, ATT_SMEM);

    // 1-3, then q-GEMM at slot #4 (ncu capture slot)
    cvt_kernel<<<NELEM/1024, 256>>>(x,   x16,  NELEM);
    cvt_kernel<<<(D_*D_)/1024, 256>>>(wq, wq16, D_*D_);
    ema_scan_kernel<<<(B_*D_)/16, 256>>>(x, l2s);
    // q = x @ wq^T -> fp16 hi/lo only
    mma_gemm_tn<0,0,2><<<dim3(D_/128, MROWS/128), blk, GEMM_SMEM>>>(
        x16, wq16, nullptr, nullptr, nullptr, nullptr, qh, ql, nullptr, MROWS, D_, D_);

    cvt3_kernel<<<dim3((D_*D_)/1024, 3), 256>>>(wk, wk16, wv, wv16, wo, wo16, D_*D_);
    cvt_kernel<<<((D_/2)*D_)/1024, 256>>>(rw1, r116, (D_/2)*D_);

    // hdn = silu(q @ rw1^T + rb1)   (uses q hi fp16)
    mma_gemm_tn<0,1,0><<<dim3((D_/2)/128, MROWS/128), blk, GEMM_SMEM>>>(
        qh, r116, nullptr, rb1, hdns, nullptr, nullptr, nullptr, nullptr, MROWS, D_/2, D_);
    // lam + fused (fp16)
    router_fuse<<<MROWS, 256>>>(hdns, rw2, rb2, x, l2s, l3m, lamp, f16);
    // kh + vh in one launch; z=0 also emits K hi/lo fp16, z=1 emits V^T fp16
    mma_gemm_tn<1,0,3><<<dim3(D_/128, MROWS/128, 2), blk, GEMM_SMEM>>>(
        f16, wk16, wv16, nullptr, khp, vhp, kh, kl, vt, MROWS, D_, D_);
    // tensor-core attention: paired q-blocks {i, 7-i}, grid (4, 32)
    attn_mma_kernel<<<dim3(4, B_*H_), blk, ATT_SMEM>>>(qh, ql, kh, kl, vt, a16);
    // out = attn @ wo^T
    mma_gemm_tn<0,0,0><<<dim3(D_/128, MROWS/128), blk, GEMM_SMEM>>>(
        a16, wo16, nullptr, nullptr, out, nullptr, nullptr, nullptr, nullptr, MROWS, D_, D_);
}